// round 4
// baseline (speedup 1.0000x reference)
#include <cuda_runtime.h>
#include <cuda_bf16.h>
#include <cstdint>
#include <cstddef>

// LSTM layer: T=2048, B=64, I=512, H=512, fp32.
//   d_out = outputs[T,B,H] ++ h_T[B,H] ++ c_T[B,H]
// Kernel A: gates_x = inp @ W_ih^T + b_ih + b_hh  (1 GiB device scratch)
// Kernel B: persistent recurrence, 128 CTAs (1/SM), two independent 64-CTA
//           groups (batch halves), flag-array barrier, cp.async h staging.

#define TSTEPS 2048
#define BATCH  64
#define IDIM   512
#define HDIM   512
#define NGATE  2048
#define MROWS  (TSTEPS * BATCH)
#define NBLK   128

__device__ float    g_gates[(size_t)MROWS * NGATE];
__device__ float    g_hbuf[2][BATCH * HDIM];
__device__ unsigned g_flags[NBLK];          // per-CTA step counters

__global__ void init_bar_kernel() {
    if (threadIdx.x < NBLK) g_flags[threadIdx.x] = 0u;
}

// ---------------------------------------------------------------------------
// Kernel A: 128x128x16 tiled fp32 GEMM with f32x2 packed FMA (near fp32 peak).
// ---------------------------------------------------------------------------
#define BM 128
#define BN 128
#define BK 16

__global__ __launch_bounds__(256)
void gemm_gates_x(const float* __restrict__ A,
                  const float* __restrict__ W,
                  const float* __restrict__ bih,
                  const float* __restrict__ bhh)
{
    __shared__ float As[BK][BM + 4];
    __shared__ float Bs[BK][BN + 4];

    const int tid = threadIdx.x;
    const int tm  = tid >> 4;
    const int tn  = tid & 15;
    const int m0  = blockIdx.y * BM;
    const int n0  = blockIdx.x * BN;

    unsigned long long acc[4][8];
#pragma unroll
    for (int p = 0; p < 4; p++)
#pragma unroll
        for (int j = 0; j < 8; j++) acc[p][j] = 0ULL;

    const int lrow = tid >> 2;
    const int lc4  = (tid & 3) * 4;

    for (int k0 = 0; k0 < IDIM; k0 += BK) {
#pragma unroll
        for (int h = 0; h < 2; h++) {
            const int r = lrow + h * 64;
            float4 va = *(const float4*)&A[(size_t)(m0 + r) * IDIM + k0 + lc4];
            As[lc4 + 0][r] = va.x; As[lc4 + 1][r] = va.y;
            As[lc4 + 2][r] = va.z; As[lc4 + 3][r] = va.w;
            float4 vb = *(const float4*)&W[(size_t)(n0 + r) * IDIM + k0 + lc4];
            Bs[lc4 + 0][r] = vb.x; Bs[lc4 + 1][r] = vb.y;
            Bs[lc4 + 2][r] = vb.z; Bs[lc4 + 3][r] = vb.w;
        }
        __syncthreads();

#pragma unroll
        for (int k = 0; k < BK; k++) {
            float4 a0 = *(const float4*)&As[k][tm * 4];
            float4 a1 = *(const float4*)&As[k][tm * 4 + 64];
            float4 b0 = *(const float4*)&Bs[k][tn * 4];
            float4 b1 = *(const float4*)&Bs[k][tn * 4 + 64];
            unsigned long long a2[4];
            a2[0] = *(unsigned long long*)&a0.x;
            a2[1] = *(unsigned long long*)&a0.z;
            a2[2] = *(unsigned long long*)&a1.x;
            a2[3] = *(unsigned long long*)&a1.z;
            float bs[8] = {b0.x, b0.y, b0.z, b0.w, b1.x, b1.y, b1.z, b1.w};
#pragma unroll
            for (int j = 0; j < 8; j++) {
                unsigned long long b2;
                asm("mov.b64 %0,{%1,%1};" : "=l"(b2) : "r"(__float_as_uint(bs[j])));
#pragma unroll
                for (int p = 0; p < 4; p++)
                    asm("fma.rn.f32x2 %0,%1,%2,%0;"
                        : "+l"(acc[p][j]) : "l"(a2[p]), "l"(b2));
            }
        }
        __syncthreads();
    }

    const int nlo = n0 + tn * 4;
    const int nhi = nlo + 64;
    float4 t1 = *(const float4*)&bih[nlo];
    float4 t2 = *(const float4*)&bhh[nlo];
    float4 blo = make_float4(t1.x + t2.x, t1.y + t2.y, t1.z + t2.z, t1.w + t2.w);
    t1 = *(const float4*)&bih[nhi];
    t2 = *(const float4*)&bhh[nhi];
    float4 bhi = make_float4(t1.x + t2.x, t1.y + t2.y, t1.z + t2.z, t1.w + t2.w);

#pragma unroll
    for (int p = 0; p < 4; p++) {
        const int prbase = (p < 2) ? (tm * 4 + 2 * p) : (64 + tm * 4 + 2 * (p - 2));
#pragma unroll
        for (int h = 0; h < 2; h++) {
            const size_t m = (size_t)(m0 + prbase + h);
            float4 vlo, vhi;
            {
                float2 f0 = *(float2*)&acc[p][0];
                float2 f1 = *(float2*)&acc[p][1];
                float2 f2 = *(float2*)&acc[p][2];
                float2 f3 = *(float2*)&acc[p][3];
                vlo = make_float4(h ? f0.y : f0.x, h ? f1.y : f1.x,
                                  h ? f2.y : f2.x, h ? f3.y : f3.x);
                float2 g0 = *(float2*)&acc[p][4];
                float2 g1 = *(float2*)&acc[p][5];
                float2 g2 = *(float2*)&acc[p][6];
                float2 g3 = *(float2*)&acc[p][7];
                vhi = make_float4(h ? g0.y : g0.x, h ? g1.y : g1.x,
                                  h ? g2.y : g2.x, h ? g3.y : g3.x);
            }
            vlo.x += blo.x; vlo.y += blo.y; vlo.z += blo.z; vlo.w += blo.w;
            vhi.x += bhi.x; vhi.y += bhi.y; vhi.z += bhi.z; vhi.w += bhi.w;
            *(float4*)&g_gates[m * NGATE + nlo] = vlo;
            *(float4*)&g_gates[m * NGATE + nhi] = vhi;
        }
    }
}

// ---------------------------------------------------------------------------
// Kernel B: persistent recurrence
// ---------------------------------------------------------------------------
__device__ __forceinline__ float fsig(float x) {
    return __fdividef(1.0f, 1.0f + __expf(-x));
}
__device__ __forceinline__ float ftanh(float x) {
    x = fminf(fmaxf(x, -15.0f), 15.0f);
    float e = __expf(-2.0f * x);
    return __fdividef(1.0f - e, 1.0f + e);
}

#define WS_FLOATS 16512           // 32 rows x 516 (stride 129 float4)
#define HS_FLOATS 16384           // 32 x 512, rotated
#define SMEM_B_BYTES ((WS_FLOATS + HS_FLOATS) * 4)   // 131584 -> 1 CTA/SM

__global__ __launch_bounds__(128, 1)
void lstm_rec(const float* __restrict__ h0,
              const float* __restrict__ c0,
              const float* __restrict__ Whh,
              float* __restrict__ out)
{
    extern __shared__ float sm[];
    float4* W_s4 = (float4*)sm;
    float4* h_s4 = (float4*)(sm + WS_FLOATS);

    const int tid  = threadIdx.x;           // 0..127
    const int cb   = blockIdx.x;
    const int half = cb & 1;                // batch-half group
    const int b0   = half * 32;
    const int j0   = (cb >> 1) * 8;
    const int w    = tid >> 5;
    const int lane = tid & 31;
    const int lb   = lane & 15;
    const int lj   = lane >> 4;
    const int jj   = w * 2 + lj;
    const int j    = j0 + jj;
    const int b1   = b0 + lb;
    const int b2   = b0 + lb + 16;

    // Stage W_hh slice once
    const float4* Whh4 = (const float4*)Whh;
#pragma unroll
    for (int i = 0; i < 32; i++) {
        int idx = tid + i * 128;
        int rr = idx >> 7, c = idx & 127;
        int R = (rr >> 3) * HDIM + j0 + (rr & 7);
        W_s4[rr * 129 + c] = Whh4[(size_t)R * 128 + c];
    }

    float c_reg1 = c0[b1 * HDIM + j];
    float c_reg2 = c0[b2 * HDIM + j];
    float h1v = 0.0f, h2v = 0.0f;

    const unsigned hbase1 = (unsigned)__cvta_generic_to_shared(h_s4 + (size_t)lb * 128);
    const unsigned hbase2 = (unsigned)__cvta_generic_to_shared(h_s4 + (size_t)(lb + 16) * 128);
    const unsigned wbase  = (unsigned)__cvta_generic_to_shared(W_s4 + (size_t)jj * 129);
    const unsigned hsm    = (unsigned)__cvta_generic_to_shared(h_s4);

    // my flag slot; the 64 slots of my group are g_flags[half*64 + 0..63]
    unsigned long long myflag =
        (unsigned long long)__cvta_generic_to_global(&g_flags[half * 64 + (cb >> 1)]);
    unsigned long long pollp =
        (unsigned long long)__cvta_generic_to_global(&g_flags[half * 64 + tid]);

    for (int t = 0; t < TSTEPS; t++) {
        // prefetch gx for both cells (consumed after dot loop, ~4K cyc later)
        const float* gxp1 = g_gates + (size_t)(t * BATCH + b1) * NGATE + j;
        const float* gxp2 = g_gates + (size_t)(t * BATCH + b2) * NGATE + j;
        float gx10 = __ldcs(gxp1);
        float gx11 = __ldcs(gxp1 + 512);
        float gx12 = __ldcs(gxp1 + 1024);
        float gx13 = __ldcs(gxp1 + 1536);
        float gx20 = __ldcs(gxp2);
        float gx21 = __ldcs(gxp2 + 512);
        float gx22 = __ldcs(gxp2 + 1024);
        float gx23 = __ldcs(gxp2 + 1536);

        // stage h for this CTA's 32 batches into rotated smem via cp.async
        const float4* hsrc = (t == 0) ? ((const float4*)h0 + (size_t)b0 * 128)
                                      : ((const float4*)g_hbuf[t & 1] + (size_t)b0 * 128);
#pragma unroll
        for (int i = 0; i < 32; i++) {
            // row i, column tid (tid < 128): dst rotated by row
            unsigned dst = hsm + (unsigned)((i * 128 + ((tid + i) & 127)) * 16);
            const float4* src = hsrc + i * 128 + tid;
            asm volatile("cp.async.cg.shared.global [%0],[%1],16;"
                         :: "r"(dst), "l"(src));
        }
        asm volatile("cp.async.commit_group;");
        asm volatile("cp.async.wait_group 0;");
        __syncthreads();

        // 8 dot products of length 512: gates i,f,g,o for batches b1,b2
        unsigned long long a00 = 0, a01 = 0, a10 = 0, a11 = 0;
        unsigned long long a20 = 0, a21 = 0, a30 = 0, a31 = 0;
#pragma unroll 4
        for (int c = 0; c < 128; c++) {
            unsigned ha1 = hbase1 + (((c + lb) & 127) << 4);
            unsigned ha2 = hbase2 + (((c + lb + 16) & 127) << 4);
            unsigned wa  = wbase + (c << 4);
            unsigned long long h1a, h1b, h2a, h2b, wva, wvb;
            asm("ld.shared.v2.b64 {%0,%1},[%2];" : "=l"(h1a), "=l"(h1b) : "r"(ha1));
            asm("ld.shared.v2.b64 {%0,%1},[%2];" : "=l"(h2a), "=l"(h2b) : "r"(ha2));
            asm("ld.shared.v2.b64 {%0,%1},[%2];" : "=l"(wva), "=l"(wvb) : "r"(wa));
            asm("fma.rn.f32x2 %0,%1,%2,%0;" : "+l"(a00) : "l"(h1a), "l"(wva));
            asm("fma.rn.f32x2 %0,%1,%2,%0;" : "+l"(a00) : "l"(h1b), "l"(wvb));
            asm("fma.rn.f32x2 %0,%1,%2,%0;" : "+l"(a01) : "l"(h2a), "l"(wva));
            asm("fma.rn.f32x2 %0,%1,%2,%0;" : "+l"(a01) : "l"(h2b), "l"(wvb));
            asm("ld.shared.v2.b64 {%0,%1},[%2+16512];" : "=l"(wva), "=l"(wvb) : "r"(wa));
            asm("fma.rn.f32x2 %0,%1,%2,%0;" : "+l"(a10) : "l"(h1a), "l"(wva));
            asm("fma.rn.f32x2 %0,%1,%2,%0;" : "+l"(a10) : "l"(h1b), "l"(wvb));
            asm("fma.rn.f32x2 %0,%1,%2,%0;" : "+l"(a11) : "l"(h2a), "l"(wva));
            asm("fma.rn.f32x2 %0,%1,%2,%0;" : "+l"(a11) : "l"(h2b), "l"(wvb));
            asm("ld.shared.v2.b64 {%0,%1},[%2+33024];" : "=l"(wva), "=l"(wvb) : "r"(wa));
            asm("fma.rn.f32x2 %0,%1,%2,%0;" : "+l"(a20) : "l"(h1a), "l"(wva));
            asm("fma.rn.f32x2 %0,%1,%2,%0;" : "+l"(a20) : "l"(h1b), "l"(wvb));
            asm("fma.rn.f32x2 %0,%1,%2,%0;" : "+l"(a21) : "l"(h2a), "l"(wva));
            asm("fma.rn.f32x2 %0,%1,%2,%0;" : "+l"(a21) : "l"(h2b), "l"(wvb));
            asm("ld.shared.v2.b64 {%0,%1},[%2+49536];" : "=l"(wva), "=l"(wvb) : "r"(wa));
            asm("fma.rn.f32x2 %0,%1,%2,%0;" : "+l"(a30) : "l"(h1a), "l"(wva));
            asm("fma.rn.f32x2 %0,%1,%2,%0;" : "+l"(a30) : "l"(h1b), "l"(wvb));
            asm("fma.rn.f32x2 %0,%1,%2,%0;" : "+l"(a31) : "l"(h2a), "l"(wva));
            asm("fma.rn.f32x2 %0,%1,%2,%0;" : "+l"(a31) : "l"(h2b), "l"(wvb));
        }

        {
            float2 f;
            f = *(float2*)&a00; float gi1 = fsig (gx10 + f.x + f.y);
            f = *(float2*)&a10; float gf1 = fsig (gx11 + f.x + f.y);
            f = *(float2*)&a20; float gg1 = ftanh(gx12 + f.x + f.y);
            f = *(float2*)&a30; float go1 = fsig (gx13 + f.x + f.y);
            c_reg1 = gf1 * c_reg1 + gi1 * gg1;
            h1v    = go1 * ftanh(c_reg1);

            f = *(float2*)&a01; float gi2 = fsig (gx20 + f.x + f.y);
            f = *(float2*)&a11; float gf2 = fsig (gx21 + f.x + f.y);
            f = *(float2*)&a21; float gg2 = ftanh(gx22 + f.x + f.y);
            f = *(float2*)&a31; float go2 = fsig (gx23 + f.x + f.y);
            c_reg2 = gf2 * c_reg2 + gi2 * gg2;
            h2v    = go2 * ftanh(c_reg2);
        }

        // publish h for next step FIRST (critical path), then arrive
        g_hbuf[(t + 1) & 1][b1 * HDIM + j] = h1v;
        g_hbuf[(t + 1) & 1][b2 * HDIM + j] = h2v;
        __syncthreads();                    // all CTA h-writes issued
        if (tid == 0) {
            asm volatile("st.release.gpu.global.u32 [%0], %1;"
                         :: "l"(myflag), "r"((unsigned)(t + 1)) : "memory");
        }

        // off-critical-path: outputs for this step
        out[(size_t)t * (BATCH * HDIM) + b1 * HDIM + j] = h1v;
        out[(size_t)t * (BATCH * HDIM) + b2 * HDIM + j] = h2v;

        // wait: 64 threads each spin on one flag of this group
        if (tid < 64) {
            unsigned v;
            do {
                asm volatile("ld.acquire.gpu.global.u32 %0, [%1];"
                             : "=r"(v) : "l"(pollp) : "memory");
            } while (v < (unsigned)(t + 1));
        }
        __syncthreads();
    }

    const size_t obase = (size_t)TSTEPS * (BATCH * HDIM);
    out[obase + b1 * HDIM + j] = h1v;
    out[obase + b2 * HDIM + j] = h2v;
    out[obase + BATCH * HDIM + b1 * HDIM + j] = c_reg1;
    out[obase + BATCH * HDIM + b2 * HDIM + j] = c_reg2;
}

// ---------------------------------------------------------------------------
extern "C" void kernel_launch(void* const* d_in, const int* in_sizes, int n_in,
                              void* d_out, int out_size) {
    const float* inp = (const float*)d_in[0];
    const float* h0  = (const float*)d_in[1];
    const float* c0  = (const float*)d_in[2];
    const float* Wih = (const float*)d_in[3];
    const float* Whh = (const float*)d_in[4];
    const float* bih = (const float*)d_in[5];
    const float* bhh = (const float*)d_in[6];
    float* out = (float*)d_out;

    cudaFuncSetAttribute(lstm_rec, cudaFuncAttributeMaxDynamicSharedMemorySize,
                         SMEM_B_BYTES);

    init_bar_kernel<<<1, NBLK>>>();
    dim3 gridA(NGATE / BN, MROWS / BM);
    gemm_gates_x<<<gridA, 256>>>(inp, Wih, bih, bhh);
    lstm_rec<<<NBLK, 128, SMEM_B_BYTES>>>(h0, c0, Whh, out);
}

// round 10
// speedup vs baseline: 1.4777x; 1.4777x over previous
#include <cuda_runtime.h>
#include <cuda_bf16.h>
#include <cstdint>
#include <cstddef>

// LSTM layer: T=2048, B=64, I=512, H=512, fp32.
//   d_out = outputs[T,B,H] ++ h_T[B,H] ++ c_T[B,H]
// Kernel S : split fp32 -> bf16 hi/lo for inp and W_ih
// Kernel A : mma.sync (HMMA bf16) split-bf16 GEMM -> g_gates (+biases)
// Kernel B : persistent recurrence (R3-proven), 128 CTAs, grid barrier/step.
// NOTE: harness builds PTX at compute_103 (no 'a') -> tcgen05 unavailable;
//       ldmatrix + mma.sync are the available tensor-core path.

#define TSTEPS 2048
#define BATCH  64
#define IDIM   512
#define HDIM   512
#define NGATE  2048
#define MROWS  (TSTEPS * BATCH)        // 131072
#define NBLK   128

__device__ float          g_gates[(size_t)MROWS * NGATE];   // 1 GiB
__device__ __nv_bfloat16  g_Ahi[(size_t)MROWS * IDIM];
__device__ __nv_bfloat16  g_Alo[(size_t)MROWS * IDIM];
__device__ __nv_bfloat16  g_Bhi[(size_t)NGATE * IDIM];
__device__ __nv_bfloat16  g_Blo[(size_t)NGATE * IDIM];
__device__ float          g_hbuf[2][BATCH * HDIM];
__device__ unsigned       g_bar;

__global__ void init_bar_kernel() { g_bar = 0u; }

// ---------------------------------------------------------------------------
// Kernel S: fp32 -> (bf16 hi, bf16 lo) split, 4 elems/thread
// ---------------------------------------------------------------------------
__global__ void split_kernel(const float* __restrict__ s,
                             __nv_bfloat16* __restrict__ hi,
                             __nv_bfloat16* __restrict__ lo, int n4)
{
    int i = blockIdx.x * 256 + threadIdx.x;
    if (i >= n4) return;
    float4 v = ((const float4*)s)[i];
    float f[4] = {v.x, v.y, v.z, v.w};
    __nv_bfloat16 h[4], l[4];
#pragma unroll
    for (int k = 0; k < 4; k++) {
        h[k] = __float2bfloat16_rn(f[k]);
        l[k] = __float2bfloat16_rn(f[k] - __bfloat162float(h[k]));
    }
    *(uint2*)(hi + (size_t)i * 4) = *(uint2*)h;
    *(uint2*)(lo + (size_t)i * 4) = *(uint2*)l;
}

// ---------------------------------------------------------------------------
// Kernel A: split-bf16 mma.sync GEMM.
// C[131072, 2048] = A[M,512] @ W[2048,512]^T   (3-term split, fp32 acc)
// Block 128x128, 256 thr (8 warps: 4 m x 2 n; warp tile 32x64).
// K chunks of 32, 2-stage cp.async pipeline.
// SMEM per stage: Ahi/Alo/Bhi/Blo, each 128 rows x 40 bf16 (stride 80 B).
// ---------------------------------------------------------------------------
#define STG_BYTES 40960                    // 4 * 128*40*2
#define GEMM_SMEM (2 * STG_BYTES)          // 81920

__device__ __forceinline__ uint32_t smem_u32(const void* p) {
    uint32_t a;
    asm("{ .reg .u64 t; cvta.to.shared.u64 t, %1; cvt.u32.u64 %0, t; }"
        : "=r"(a) : "l"(p));
    return a;
}

__device__ __forceinline__ void ldsm4(uint32_t* r, uint32_t addr) {
    asm volatile("ldmatrix.sync.aligned.m8n8.x4.shared.b16 {%0,%1,%2,%3},[%4];"
                 : "=r"(r[0]), "=r"(r[1]), "=r"(r[2]), "=r"(r[3]) : "r"(addr));
}
__device__ __forceinline__ void hmma(float* d, const uint32_t* a, const uint32_t* b) {
    asm volatile("mma.sync.aligned.m16n8k16.row.col.f32.bf16.bf16.f32 "
                 "{%0,%1,%2,%3},{%4,%5,%6,%7},{%8,%9},{%0,%1,%2,%3};"
                 : "+f"(d[0]), "+f"(d[1]), "+f"(d[2]), "+f"(d[3])
                 : "r"(a[0]), "r"(a[1]), "r"(a[2]), "r"(a[3]),
                   "r"(b[0]), "r"(b[1]));
}

__global__ __launch_bounds__(256, 1)
void gemm_mma(const float* __restrict__ bih, const float* __restrict__ bhh)
{
    extern __shared__ char smem[];
    const uint32_t sbase = smem_u32(smem);

    const int tid  = threadIdx.x;
    const int wid  = tid >> 5, lane = tid & 31;
    const int wm   = wid & 3;          // warp m 0..3 (32 rows each)
    const int wn   = wid >> 2;         // warp n 0..1 (64 cols each)
    const int n0   = blockIdx.x * 128;
    const size_t m0 = (size_t)blockIdx.y * 128;

    // buffer offsets within a stage (bytes)
    const int OF_AHI = 0, OF_ALO = 10240, OF_BHI = 20480, OF_BLO = 30720;

    // --- per-thread ldmatrix addresses (byte offsets within a buffer) ---
    const int lm = lane >> 3, lr = lane & 7;
    uint32_t addrA[2], addrB[4];
#pragma unroll
    for (int mt = 0; mt < 2; mt++) {
        int row = wm * 32 + mt * 16 + (lm & 1) * 8 + lr;
        addrA[mt] = (uint32_t)(row * 80 + (lm >> 1) * 16);
    }
#pragma unroll
    for (int p = 0; p < 4; p++) {
        int row = wn * 64 + p * 16 + (lm >> 1) * 8 + lr;
        addrB[p] = (uint32_t)(row * 80 + (lm & 1) * 16);
    }

    // --- staging source pointers (16B chunks; each thread 2 chunks/buffer) ---
    // chunk idx: row = idx>>2, c8 = idx&3
    const __nv_bfloat16* srcA_hi = g_Ahi + m0 * 512;
    const __nv_bfloat16* srcA_lo = g_Alo + m0 * 512;
    const __nv_bfloat16* srcB_hi = g_Bhi + (size_t)n0 * 512;
    const __nv_bfloat16* srcB_lo = g_Blo + (size_t)n0 * 512;

    float acc[2][8][4];
#pragma unroll
    for (int mt = 0; mt < 2; mt++)
#pragma unroll
        for (int nt = 0; nt < 8; nt++)
#pragma unroll
            for (int q = 0; q < 4; q++) acc[mt][nt][q] = 0.0f;

    auto stage = [&](int kc, int st) {
        const uint32_t sb = sbase + st * STG_BYTES;
#pragma unroll
        for (int it = 0; it < 2; it++) {
            int idx = tid + it * 256;           // 0..511
            int row = idx >> 2, c8 = idx & 3;
            uint32_t doff = (uint32_t)(row * 80 + c8 * 16);
            const __nv_bfloat16* sa = srcA_hi + (size_t)row * 512 + kc * 32 + c8 * 8;
            const __nv_bfloat16* sb2 = srcA_lo + (size_t)row * 512 + kc * 32 + c8 * 8;
            const __nv_bfloat16* sc = srcB_hi + (size_t)row * 512 + kc * 32 + c8 * 8;
            const __nv_bfloat16* sd = srcB_lo + (size_t)row * 512 + kc * 32 + c8 * 8;
            asm volatile("cp.async.cg.shared.global [%0],[%1],16;"
                         :: "r"(sb + OF_AHI + doff), "l"(sa));
            asm volatile("cp.async.cg.shared.global [%0],[%1],16;"
                         :: "r"(sb + OF_ALO + doff), "l"(sb2));
            asm volatile("cp.async.cg.shared.global [%0],[%1],16;"
                         :: "r"(sb + OF_BHI + doff), "l"(sc));
            asm volatile("cp.async.cg.shared.global [%0],[%1],16;"
                         :: "r"(sb + OF_BLO + doff), "l"(sd));
        }
        asm volatile("cp.async.commit_group;");
    };

    stage(0, 0);

    for (int kc = 0; kc < 16; kc++) {
        const int st = kc & 1;
        if (kc + 1 < 16) {
            stage(kc + 1, st ^ 1);
            asm volatile("cp.async.wait_group 1;");
        } else {
            asm volatile("cp.async.wait_group 0;");
        }
        __syncthreads();

        const uint32_t sb = sbase + st * STG_BYTES;
#pragma unroll
        for (int ks = 0; ks < 2; ks++) {
            const uint32_t ko = (uint32_t)(ks * 32);
            uint32_t ahi[2][4], alo[2][4], bhi[8][2], blo[8][2];
#pragma unroll
            for (int mt = 0; mt < 2; mt++) {
                ldsm4(ahi[mt], sb + OF_AHI + addrA[mt] + ko);
                ldsm4(alo[mt], sb + OF_ALO + addrA[mt] + ko);
            }
#pragma unroll
            for (int p = 0; p < 4; p++) {
                uint32_t r[4];
                ldsm4(r, sb + OF_BHI + addrB[p] + ko);
                bhi[p * 2][0] = r[0]; bhi[p * 2][1] = r[1];
                bhi[p * 2 + 1][0] = r[2]; bhi[p * 2 + 1][1] = r[3];
                ldsm4(r, sb + OF_BLO + addrB[p] + ko);
                blo[p * 2][0] = r[0]; blo[p * 2][1] = r[1];
                blo[p * 2 + 1][0] = r[2]; blo[p * 2 + 1][1] = r[3];
            }
#pragma unroll
            for (int mt = 0; mt < 2; mt++)
#pragma unroll
                for (int nt = 0; nt < 8; nt++) {
                    hmma(acc[mt][nt], ahi[mt], bhi[nt]);
                    hmma(acc[mt][nt], ahi[mt], blo[nt]);
                    hmma(acc[mt][nt], alo[mt], bhi[nt]);
                }
        }
        __syncthreads();
    }

    // epilogue: + (b_ih + b_hh), write float2 pairs
    const int cq = (lane & 3) * 2, rq = lane >> 2;
#pragma unroll
    for (int nt = 0; nt < 8; nt++) {
        const int col = n0 + wn * 64 + nt * 8 + cq;
        float2 bsum;
        bsum.x = bih[col]     + bhh[col];
        bsum.y = bih[col + 1] + bhh[col + 1];
#pragma unroll
        for (int mt = 0; mt < 2; mt++) {
            const size_t r0 = m0 + wm * 32 + mt * 16 + rq;
            float2 v0 = make_float2(acc[mt][nt][0] + bsum.x, acc[mt][nt][1] + bsum.y);
            float2 v1 = make_float2(acc[mt][nt][2] + bsum.x, acc[mt][nt][3] + bsum.y);
            *(float2*)&g_gates[r0 * NGATE + col]       = v0;
            *(float2*)&g_gates[(r0 + 8) * NGATE + col] = v1;
        }
    }
}

// ---------------------------------------------------------------------------
// Kernel B: persistent recurrence (R3-proven version, unchanged)
// ---------------------------------------------------------------------------
__device__ __forceinline__ float fsig(float x) {
    return __fdividef(1.0f, 1.0f + __expf(-x));
}
__device__ __forceinline__ float ftanh(float x) {
    x = fminf(fmaxf(x, -15.0f), 15.0f);
    float e = __expf(-2.0f * x);
    return __fdividef(1.0f - e, 1.0f + e);
}

#define WS_FLOATS 16512
#define HS_FLOATS 16384
#define SMEM_B_BYTES ((WS_FLOATS + HS_FLOATS) * 4)   // 131584 -> 1 CTA/SM

__global__ __launch_bounds__(128, 1)
void lstm_rec(const float* __restrict__ h0,
              const float* __restrict__ c0,
              const float* __restrict__ Whh,
              float* __restrict__ out)
{
    extern __shared__ float sm[];
    float4* W_s4 = (float4*)sm;
    float4* h_s4 = (float4*)(sm + WS_FLOATS);

    const int tid  = threadIdx.x;
    const int cb   = blockIdx.x;
    const int b0   = (cb & 1) * 32;
    const int j0   = (cb >> 1) * 8;
    const int w    = tid >> 5;
    const int lane = tid & 31;
    const int lb   = lane & 15;
    const int lj   = lane >> 4;
    const int jj   = w * 2 + lj;
    const int j    = j0 + jj;
    const int b1   = b0 + lb;
    const int b2   = b0 + lb + 16;

    const float4* Whh4 = (const float4*)Whh;
#pragma unroll
    for (int i = 0; i < 32; i++) {
        int idx = tid + i * 128;
        int rr = idx >> 7, c = idx & 127;
        int R = (rr >> 3) * HDIM + j0 + (rr & 7);
        W_s4[rr * 129 + c] = Whh4[(size_t)R * 128 + c];
    }

    float c_reg1 = c0[b1 * HDIM + j];
    float c_reg2 = c0[b2 * HDIM + j];
    float h1v = 0.0f, h2v = 0.0f;

    const unsigned hbase1 = (unsigned)__cvta_generic_to_shared(h_s4 + (size_t)lb * 128);
    const unsigned hbase2 = (unsigned)__cvta_generic_to_shared(h_s4 + (size_t)(lb + 16) * 128);
    const unsigned wbase  = (unsigned)__cvta_generic_to_shared(W_s4 + (size_t)jj * 129);
    unsigned long long barp = (unsigned long long)__cvta_generic_to_global(&g_bar);

    for (int t = 0; t < TSTEPS; t++) {
        const float* gxp1 = g_gates + (size_t)(t * BATCH + b1) * NGATE + j;
        const float* gxp2 = g_gates + (size_t)(t * BATCH + b2) * NGATE + j;
        float gx10 = __ldcs(gxp1);
        float gx11 = __ldcs(gxp1 + 512);
        float gx12 = __ldcs(gxp1 + 1024);
        float gx13 = __ldcs(gxp1 + 1536);
        float gx20 = __ldcs(gxp2);
        float gx21 = __ldcs(gxp2 + 512);
        float gx22 = __ldcs(gxp2 + 1024);
        float gx23 = __ldcs(gxp2 + 1536);

        const float4* hsrc = (t == 0) ? ((const float4*)h0 + (size_t)b0 * 128)
                                      : ((const float4*)g_hbuf[t & 1] + (size_t)b0 * 128);
#pragma unroll
        for (int i = 0; i < 32; i++) {
            int idx = tid + i * 128;
            int rbl = idx >> 7, c = idx & 127;
            h_s4[rbl * 128 + ((c + rbl) & 127)] = hsrc[rbl * 128 + c];
        }
        __syncthreads();

        unsigned long long a00 = 0, a01 = 0, a10 = 0, a11 = 0;
        unsigned long long a20 = 0, a21 = 0, a30 = 0, a31 = 0;
#pragma unroll 4
        for (int c = 0; c < 128; c++) {
            unsigned ha1 = hbase1 + (((c + lb) & 127) << 4);
            unsigned ha2 = hbase2 + (((c + lb + 16) & 127) << 4);
            unsigned wa  = wbase + (c << 4);
            unsigned long long h1a, h1b, h2a, h2b, wva, wvb;
            asm("ld.shared.v2.b64 {%0,%1},[%2];" : "=l"(h1a), "=l"(h1b) : "r"(ha1));
            asm("ld.shared.v2.b64 {%0,%1},[%2];" : "=l"(h2a), "=l"(h2b) : "r"(ha2));
            asm("ld.shared.v2.b64 {%0,%1},[%2];" : "=l"(wva), "=l"(wvb) : "r"(wa));
            asm("fma.rn.f32x2 %0,%1,%2,%0;" : "+l"(a00) : "l"(h1a), "l"(wva));
            asm("fma.rn.f32x2 %0,%1,%2,%0;" : "+l"(a00) : "l"(h1b), "l"(wvb));
            asm("fma.rn.f32x2 %0,%1,%2,%0;" : "+l"(a01) : "l"(h2a), "l"(wva));
            asm("fma.rn.f32x2 %0,%1,%2,%0;" : "+l"(a01) : "l"(h2b), "l"(wvb));
            asm("ld.shared.v2.b64 {%0,%1},[%2+16512];" : "=l"(wva), "=l"(wvb) : "r"(wa));
            asm("fma.rn.f32x2 %0,%1,%2,%0;" : "+l"(a10) : "l"(h1a), "l"(wva));
            asm("fma.rn.f32x2 %0,%1,%2,%0;" : "+l"(a10) : "l"(h1b), "l"(wvb));
            asm("fma.rn.f32x2 %0,%1,%2,%0;" : "+l"(a11) : "l"(h2a), "l"(wva));
            asm("fma.rn.f32x2 %0,%1,%2,%0;" : "+l"(a11) : "l"(h2b), "l"(wvb));
            asm("ld.shared.v2.b64 {%0,%1},[%2+33024];" : "=l"(wva), "=l"(wvb) : "r"(wa));
            asm("fma.rn.f32x2 %0,%1,%2,%0;" : "+l"(a20) : "l"(h1a), "l"(wva));
            asm("fma.rn.f32x2 %0,%1,%2,%0;" : "+l"(a20) : "l"(h1b), "l"(wvb));
            asm("fma.rn.f32x2 %0,%1,%2,%0;" : "+l"(a21) : "l"(h2a), "l"(wva));
            asm("fma.rn.f32x2 %0,%1,%2,%0;" : "+l"(a21) : "l"(h2b), "l"(wvb));
            asm("ld.shared.v2.b64 {%0,%1},[%2+49536];" : "=l"(wva), "=l"(wvb) : "r"(wa));
            asm("fma.rn.f32x2 %0,%1,%2,%0;" : "+l"(a30) : "l"(h1a), "l"(wva));
            asm("fma.rn.f32x2 %0,%1,%2,%0;" : "+l"(a30) : "l"(h1b), "l"(wvb));
            asm("fma.rn.f32x2 %0,%1,%2,%0;" : "+l"(a31) : "l"(h2a), "l"(wva));
            asm("fma.rn.f32x2 %0,%1,%2,%0;" : "+l"(a31) : "l"(h2b), "l"(wvb));
        }

        {
            float2 f;
            f = *(float2*)&a00; float gi1 = fsig (gx10 + f.x + f.y);
            f = *(float2*)&a10; float gf1 = fsig (gx11 + f.x + f.y);
            f = *(float2*)&a20; float gg1 = ftanh(gx12 + f.x + f.y);
            f = *(float2*)&a30; float go1 = fsig (gx13 + f.x + f.y);
            c_reg1 = gf1 * c_reg1 + gi1 * gg1;
            h1v    = go1 * ftanh(c_reg1);

            f = *(float2*)&a01; float gi2 = fsig (gx20 + f.x + f.y);
            f = *(float2*)&a11; float gf2 = fsig (gx21 + f.x + f.y);
            f = *(float2*)&a21; float gg2 = ftanh(gx22 + f.x + f.y);
            f = *(float2*)&a31; float go2 = fsig (gx23 + f.x + f.y);
            c_reg2 = gf2 * c_reg2 + gi2 * gg2;
            h2v    = go2 * ftanh(c_reg2);
        }

        out[(size_t)t * (BATCH * HDIM) + b1 * HDIM + j] = h1v;
        out[(size_t)t * (BATCH * HDIM) + b2 * HDIM + j] = h2v;
        g_hbuf[(t + 1) & 1][b1 * HDIM + j] = h1v;
        g_hbuf[(t + 1) & 1][b2 * HDIM + j] = h2v;

        __syncthreads();
        if (tid == 0) {
            __threadfence();
            asm volatile("red.release.gpu.global.add.u32 [%0], %1;"
                         :: "l"(barp), "r"(1u) : "memory");
            const unsigned target = (unsigned)(t + 1) * NBLK;
            unsigned v;
            do {
                asm volatile("ld.acquire.gpu.global.u32 %0, [%1];"
                             : "=r"(v) : "l"(barp) : "memory");
            } while (v < target);
        }
        __syncthreads();
    }

    const size_t obase = (size_t)TSTEPS * (BATCH * HDIM);
    out[obase + b1 * HDIM + j] = h1v;
    out[obase + b2 * HDIM + j] = h2v;
    out[obase + BATCH * HDIM + b1 * HDIM + j] = c_reg1;
    out[obase + BATCH * HDIM + b2 * HDIM + j] = c_reg2;
}

// ---------------------------------------------------------------------------
extern "C" void kernel_launch(void* const* d_in, const int* in_sizes, int n_in,
                              void* d_out, int out_size) {
    const float* inp = (const float*)d_in[0];
    const float* h0  = (const float*)d_in[1];
    const float* c0  = (const float*)d_in[2];
    const float* Wih = (const float*)d_in[3];
    const float* Whh = (const float*)d_in[4];
    const float* bih = (const float*)d_in[5];
    const float* bhh = (const float*)d_in[6];
    float* out = (float*)d_out;

    cudaFuncSetAttribute(gemm_mma, cudaFuncAttributeMaxDynamicSharedMemorySize,
                         GEMM_SMEM);
    cudaFuncSetAttribute(lstm_rec, cudaFuncAttributeMaxDynamicSharedMemorySize,
                         SMEM_B_BYTES);

    __nv_bfloat16 *ahi, *alo, *bhi, *blo;
    cudaGetSymbolAddress((void**)&ahi, g_Ahi);
    cudaGetSymbolAddress((void**)&alo, g_Alo);
    cudaGetSymbolAddress((void**)&bhi, g_Bhi);
    cudaGetSymbolAddress((void**)&blo, g_Blo);

    split_kernel<<<(MROWS * IDIM / 4 + 255) / 256, 256>>>(inp, ahi, alo,
                                                          MROWS * IDIM / 4);
    split_kernel<<<(NGATE * IDIM / 4 + 255) / 256, 256>>>(Wih, bhi, blo,
                                                          NGATE * IDIM / 4);

    dim3 gridA(NGATE / 128, MROWS / 128);   // (16, 1024)
    gemm_mma<<<gridA, 256, GEMM_SMEM>>>(bih, bhh);

    init_bar_kernel<<<1, 1>>>();
    lstm_rec<<<NBLK, 128, SMEM_B_BYTES>>>(h0, c0, Whh, out);
}

// round 12
// speedup vs baseline: 2.2733x; 1.5384x over previous
#include <cuda_runtime.h>
#include <cuda_bf16.h>
#include <cstdint>
#include <cstddef>

// LSTM layer: T=2048, B=64, I=512, H=512, fp32.
//   d_out = outputs[T,B,H] ++ h_T[B,H] ++ c_T[B,H]
// Kernel S : split fp32 -> bf16 hi/lo for inp and W_ih
// Kernel A : mma.sync (HMMA bf16) split-bf16 GEMM -> g_gates (+biases) [R10-proven]
// Kernel I : reset barrier + convert h0 -> bf16 hi/lo
// Kernel B : persistent recurrence with HMMA split-bf16 recurrent GEMM.
//            128 CTAs (1/SM), grid barrier/step, h propagated as bf16 hi/lo.

#define TSTEPS 2048
#define BATCH  64
#define IDIM   512
#define HDIM   512
#define NGATE  2048
#define MROWS  (TSTEPS * BATCH)
#define NBLK   128

__device__ float          g_gates[(size_t)MROWS * NGATE];   // 1 GiB
__device__ __nv_bfloat16  g_Ahi[(size_t)MROWS * IDIM];
__device__ __nv_bfloat16  g_Alo[(size_t)MROWS * IDIM];
__device__ __nv_bfloat16  g_Bhi[(size_t)NGATE * IDIM];
__device__ __nv_bfloat16  g_Blo[(size_t)NGATE * IDIM];
__device__ __nv_bfloat16  g_hbuf_hi[2][BATCH * HDIM];
__device__ __nv_bfloat16  g_hbuf_lo[2][BATCH * HDIM];
__device__ unsigned       g_bar;

// ---------------------------------------------------------------------------
// Kernel I: reset barrier + h0 -> bf16 hi/lo into buffer 0
// ---------------------------------------------------------------------------
__global__ void init_kernel(const float* __restrict__ h0) {
    int i = blockIdx.x * 256 + threadIdx.x;
    if (i == 0) g_bar = 0u;
    if (i < BATCH * HDIM) {
        float v = h0[i];
        __nv_bfloat16 hi = __float2bfloat16_rn(v);
        __nv_bfloat16 lo = __float2bfloat16_rn(v - __bfloat162float(hi));
        g_hbuf_hi[0][i] = hi;
        g_hbuf_lo[0][i] = lo;
    }
}

// ---------------------------------------------------------------------------
// Kernel S: fp32 -> (bf16 hi, bf16 lo) split, 4 elems/thread
// ---------------------------------------------------------------------------
__global__ void split_kernel(const float* __restrict__ s,
                             __nv_bfloat16* __restrict__ hi,
                             __nv_bfloat16* __restrict__ lo, int n4)
{
    int i = blockIdx.x * 256 + threadIdx.x;
    if (i >= n4) return;
    float4 v = ((const float4*)s)[i];
    float f[4] = {v.x, v.y, v.z, v.w};
    __nv_bfloat16 h[4], l[4];
#pragma unroll
    for (int k = 0; k < 4; k++) {
        h[k] = __float2bfloat16_rn(f[k]);
        l[k] = __float2bfloat16_rn(f[k] - __bfloat162float(h[k]));
    }
    *(uint2*)(hi + (size_t)i * 4) = *(uint2*)h;
    *(uint2*)(lo + (size_t)i * 4) = *(uint2*)l;
}

// ---------------------------------------------------------------------------
// shared helpers
// ---------------------------------------------------------------------------
__device__ __forceinline__ uint32_t smem_u32(const void* p) {
    uint32_t a;
    asm("{ .reg .u64 t; cvta.to.shared.u64 t, %1; cvt.u32.u64 %0, t; }"
        : "=r"(a) : "l"(p));
    return a;
}
__device__ __forceinline__ void ldsm4(uint32_t* r, uint32_t addr) {
    asm volatile("ldmatrix.sync.aligned.m8n8.x4.shared.b16 {%0,%1,%2,%3},[%4];"
                 : "=r"(r[0]), "=r"(r[1]), "=r"(r[2]), "=r"(r[3]) : "r"(addr));
}
__device__ __forceinline__ void hmma(float* d, const uint32_t* a, const uint32_t* b) {
    asm volatile("mma.sync.aligned.m16n8k16.row.col.f32.bf16.bf16.f32 "
                 "{%0,%1,%2,%3},{%4,%5,%6,%7},{%8,%9},{%0,%1,%2,%3};"
                 : "+f"(d[0]), "+f"(d[1]), "+f"(d[2]), "+f"(d[3])
                 : "r"(a[0]), "r"(a[1]), "r"(a[2]), "r"(a[3]),
                   "r"(b[0]), "r"(b[1]));
}

// ---------------------------------------------------------------------------
// Kernel A: split-bf16 mma.sync GEMM (R10-proven, unchanged)
// ---------------------------------------------------------------------------
#define STG_BYTES 40960
#define GEMM_SMEM (2 * STG_BYTES)

__global__ __launch_bounds__(256, 1)
void gemm_mma(const float* __restrict__ bih, const float* __restrict__ bhh)
{
    extern __shared__ char smem[];
    const uint32_t sbase = smem_u32(smem);

    const int tid  = threadIdx.x;
    const int wid  = tid >> 5, lane = tid & 31;
    const int wm   = wid & 3;
    const int wn   = wid >> 2;
    const int n0   = blockIdx.x * 128;
    const size_t m0 = (size_t)blockIdx.y * 128;

    const int OF_AHI = 0, OF_ALO = 10240, OF_BHI = 20480, OF_BLO = 30720;

    const int lm = lane >> 3, lr = lane & 7;
    uint32_t addrA[2], addrB[4];
#pragma unroll
    for (int mt = 0; mt < 2; mt++) {
        int row = wm * 32 + mt * 16 + (lm & 1) * 8 + lr;
        addrA[mt] = (uint32_t)(row * 80 + (lm >> 1) * 16);
    }
#pragma unroll
    for (int p = 0; p < 4; p++) {
        int row = wn * 64 + p * 16 + (lm >> 1) * 8 + lr;
        addrB[p] = (uint32_t)(row * 80 + (lm & 1) * 16);
    }

    const __nv_bfloat16* srcA_hi = g_Ahi + m0 * 512;
    const __nv_bfloat16* srcA_lo = g_Alo + m0 * 512;
    const __nv_bfloat16* srcB_hi = g_Bhi + (size_t)n0 * 512;
    const __nv_bfloat16* srcB_lo = g_Blo + (size_t)n0 * 512;

    float acc[2][8][4];
#pragma unroll
    for (int mt = 0; mt < 2; mt++)
#pragma unroll
        for (int nt = 0; nt < 8; nt++)
#pragma unroll
            for (int q = 0; q < 4; q++) acc[mt][nt][q] = 0.0f;

    auto stage = [&](int kc, int st) {
        const uint32_t sb = sbase + st * STG_BYTES;
#pragma unroll
        for (int it = 0; it < 2; it++) {
            int idx = tid + it * 256;
            int row = idx >> 2, c8 = idx & 3;
            uint32_t doff = (uint32_t)(row * 80 + c8 * 16);
            const __nv_bfloat16* sa = srcA_hi + (size_t)row * 512 + kc * 32 + c8 * 8;
            const __nv_bfloat16* sb2 = srcA_lo + (size_t)row * 512 + kc * 32 + c8 * 8;
            const __nv_bfloat16* sc = srcB_hi + (size_t)row * 512 + kc * 32 + c8 * 8;
            const __nv_bfloat16* sd = srcB_lo + (size_t)row * 512 + kc * 32 + c8 * 8;
            asm volatile("cp.async.cg.shared.global [%0],[%1],16;"
                         :: "r"(sb + OF_AHI + doff), "l"(sa));
            asm volatile("cp.async.cg.shared.global [%0],[%1],16;"
                         :: "r"(sb + OF_ALO + doff), "l"(sb2));
            asm volatile("cp.async.cg.shared.global [%0],[%1],16;"
                         :: "r"(sb + OF_BHI + doff), "l"(sc));
            asm volatile("cp.async.cg.shared.global [%0],[%1],16;"
                         :: "r"(sb + OF_BLO + doff), "l"(sd));
        }
        asm volatile("cp.async.commit_group;");
    };

    stage(0, 0);

    for (int kc = 0; kc < 16; kc++) {
        const int st = kc & 1;
        if (kc + 1 < 16) {
            stage(kc + 1, st ^ 1);
            asm volatile("cp.async.wait_group 1;");
        } else {
            asm volatile("cp.async.wait_group 0;");
        }
        __syncthreads();

        const uint32_t sb = sbase + st * STG_BYTES;
#pragma unroll
        for (int ks = 0; ks < 2; ks++) {
            const uint32_t ko = (uint32_t)(ks * 32);
            uint32_t ahi[2][4], alo[2][4], bhi[8][2], blo[8][2];
#pragma unroll
            for (int mt = 0; mt < 2; mt++) {
                ldsm4(ahi[mt], sb + OF_AHI + addrA[mt] + ko);
                ldsm4(alo[mt], sb + OF_ALO + addrA[mt] + ko);
            }
#pragma unroll
            for (int p = 0; p < 4; p++) {
                uint32_t r[4];
                ldsm4(r, sb + OF_BHI + addrB[p] + ko);
                bhi[p * 2][0] = r[0]; bhi[p * 2][1] = r[1];
                bhi[p * 2 + 1][0] = r[2]; bhi[p * 2 + 1][1] = r[3];
                ldsm4(r, sb + OF_BLO + addrB[p] + ko);
                blo[p * 2][0] = r[0]; blo[p * 2][1] = r[1];
                blo[p * 2 + 1][0] = r[2]; blo[p * 2 + 1][1] = r[3];
            }
#pragma unroll
            for (int mt = 0; mt < 2; mt++)
#pragma unroll
                for (int nt = 0; nt < 8; nt++) {
                    hmma(acc[mt][nt], ahi[mt], bhi[nt]);
                    hmma(acc[mt][nt], ahi[mt], blo[nt]);
                    hmma(acc[mt][nt], alo[mt], bhi[nt]);
                }
        }
        __syncthreads();
    }

    const int cq = (lane & 3) * 2, rq = lane >> 2;
#pragma unroll
    for (int nt = 0; nt < 8; nt++) {
        const int col = n0 + wn * 64 + nt * 8 + cq;
        float2 bsum;
        bsum.x = bih[col]     + bhh[col];
        bsum.y = bih[col + 1] + bhh[col + 1];
#pragma unroll
        for (int mt = 0; mt < 2; mt++) {
            const size_t r0 = m0 + wm * 32 + mt * 16 + rq;
            float2 v0 = make_float2(acc[mt][nt][0] + bsum.x, acc[mt][nt][1] + bsum.y);
            float2 v1 = make_float2(acc[mt][nt][2] + bsum.x, acc[mt][nt][3] + bsum.y);
            *(float2*)&g_gates[r0 * NGATE + col]       = v0;
            *(float2*)&g_gates[(r0 + 8) * NGATE + col] = v1;
        }
    }
}

// ---------------------------------------------------------------------------
// Kernel B: persistent recurrence with HMMA recurrent GEMM
// CTA: 32 batches x 8 j (=32 N-cols: n = jj*4 + gate). 128 thr, 4 warps.
// SMEM rows stride 1040 B (conflict-free ldmatrix).
// ---------------------------------------------------------------------------
__device__ __forceinline__ float fsig(float x) {
    return __fdividef(1.0f, 1.0f + __expf(-x));
}
__device__ __forceinline__ float ftanh(float x) {
    x = fminf(fmaxf(x, -15.0f), 15.0f);
    float e = __expf(-2.0f * x);
    return __fdividef(1.0f - e, 1.0f + e);
}

#define RSTR    1040
#define OFF_WHI 0
#define OFF_WLO 33280
#define OFF_HHI 66560
#define OFF_HLO 99840
#define OFF_ACC 133120                 // 32 x 36 fp32 = 4608 B
#define REC_SMEM (OFF_ACC + 4608)      // 137728 -> 1 CTA/SM

__global__ __launch_bounds__(128, 1)
void lstm_rec(const float* __restrict__ c0,
              const float* __restrict__ Whh,
              float* __restrict__ out)
{
    extern __shared__ char smem[];
    const uint32_t sbase = smem_u32(smem);
    float* accbuf = (float*)(smem + OFF_ACC);

    const int tid  = threadIdx.x;
    const int cb   = blockIdx.x;
    const int b0   = (cb & 1) * 32;
    const int j0   = (cb >> 1) * 8;
    const int wid  = tid >> 5, lane = tid & 31;
    const int wm   = wid & 1, wn = wid >> 1;

    // --- stage W_hh (split to bf16 hi/lo) once: 32 rows (n=jj*4+g) x 512 ---
#pragma unroll
    for (int i = 0; i < 32; i++) {
        int idx = tid + i * 128;           // 0..4095 float4 chunks
        int row = idx >> 7, c4 = idx & 127;
        int R = (row & 3) * HDIM + j0 + (row >> 2);   // g*512 + j0 + jj
        float4 v = *(const float4*)&Whh[(size_t)R * HDIM + c4 * 4];
        float f[4] = {v.x, v.y, v.z, v.w};
        __nv_bfloat16 h[4], l[4];
#pragma unroll
        for (int q = 0; q < 4; q++) {
            h[q] = __float2bfloat16_rn(f[q]);
            l[q] = __float2bfloat16_rn(f[q] - __bfloat162float(h[q]));
        }
        *(uint2*)(smem + OFF_WHI + row * RSTR + c4 * 8) = *(uint2*)h;
        *(uint2*)(smem + OFF_WLO + row * RSTR + c4 * 8) = *(uint2*)l;
    }

    // --- per-thread cell mapping: bl = tid>>2 (batch), jjp = tid&3 (j pair) ---
    const int bl  = tid >> 2;
    const int jjp = tid & 3;
    const int b   = b0 + bl;
    const int jA  = j0 + jjp * 2;          // two adjacent j

    float cA = c0[b * HDIM + jA];
    float cB = c0[b * HDIM + jA + 1];
    float hA = 0.0f, hB = 0.0f;

    // --- ldmatrix addresses (R10-proven lane mapping) ---
    const int lm = lane >> 3, lr = lane & 7;
    const uint32_t aAddr = sbase + OFF_HHI
        + (uint32_t)((wm * 16 + (lm & 1) * 8 + lr) * RSTR + (lm >> 1) * 16);
    const uint32_t bAddr = sbase + OFF_WHI
        + (uint32_t)((wn * 16 + (lm >> 1) * 8 + lr) * RSTR + (lm & 1) * 16);
    const uint32_t LO = 33280;             // hi -> lo buffer delta

    unsigned long long barp = (unsigned long long)__cvta_generic_to_global(&g_bar);

    for (int t = 0; t < TSTEPS; t++) {
        // prefetch gx for both cells
        const float* gxp = g_gates + (size_t)(t * BATCH + b) * NGATE + jA;
        float gxA0 = __ldcs(gxp);
        float gxA1 = __ldcs(gxp + 512);
        float gxA2 = __ldcs(gxp + 1024);
        float gxA3 = __ldcs(gxp + 1536);
        float gxB0 = __ldcs(gxp + 1);
        float gxB1 = __ldcs(gxp + 513);
        float gxB2 = __ldcs(gxp + 1025);
        float gxB3 = __ldcs(gxp + 1537);

        // stage h hi/lo (32 batches x 512 bf16 each) via cp.async
        const __nv_bfloat16* shi = g_hbuf_hi[t & 1] + (size_t)b0 * HDIM;
        const __nv_bfloat16* slo = g_hbuf_lo[t & 1] + (size_t)b0 * HDIM;
#pragma unroll
        for (int i = 0; i < 16; i++) {
            int idx = tid + i * 128;       // 0..2047
            int row = idx >> 6, c = idx & 63;
            uint32_t doff = (uint32_t)(row * RSTR + c * 16);
            asm volatile("cp.async.cg.shared.global [%0],[%1],16;"
                         :: "r"(sbase + OFF_HHI + doff), "l"(shi + row * 512 + c * 8));
            asm volatile("cp.async.cg.shared.global [%0],[%1],16;"
                         :: "r"(sbase + OFF_HLO + doff), "l"(slo + row * 512 + c * 8));
        }
        asm volatile("cp.async.commit_group;");
        asm volatile("cp.async.wait_group 0;");
        __syncthreads();

        // --- HMMA mainloop: M16 x N16 per warp, K=512, 3-term split ---
        float accP[8], accQ[8];
#pragma unroll
        for (int q = 0; q < 8; q++) { accP[q] = 0.0f; accQ[q] = 0.0f; }

#pragma unroll 8
        for (int ks = 0; ks < 32; ks++) {
            const uint32_t ko = (uint32_t)(ks * 32);
            uint32_t ahi[4], alo[4], bhi[4], blo[4];
            ldsm4(ahi, aAddr + ko);
            ldsm4(alo, aAddr + LO + ko);
            ldsm4(bhi, bAddr + ko);
            ldsm4(blo, bAddr + LO + ko);
            hmma(accP + 0, ahi, bhi + 0);
            hmma(accP + 4, ahi, bhi + 2);
            hmma(accQ + 0, ahi, blo + 0);
            hmma(accQ + 4, ahi, blo + 2);
            hmma(accQ + 0, alo, bhi + 0);
            hmma(accQ + 4, alo, bhi + 2);
        }

        // STS acc to exchange buffer (rows=batch 0..31, cols=n 0..31, stride 36)
        {
            const int crow = lane >> 2, ccol = (lane & 3) * 2;
#pragma unroll
            for (int nt = 0; nt < 2; nt++) {
                const int col = wn * 16 + nt * 8 + ccol;
                float2 v0 = make_float2(accP[nt * 4 + 0] + accQ[nt * 4 + 0],
                                        accP[nt * 4 + 1] + accQ[nt * 4 + 1]);
                float2 v1 = make_float2(accP[nt * 4 + 2] + accQ[nt * 4 + 2],
                                        accP[nt * 4 + 3] + accQ[nt * 4 + 3]);
                *(float2*)&accbuf[(wm * 16 + crow) * 36 + col]     = v0;
                *(float2*)&accbuf[(wm * 16 + crow + 8) * 36 + col] = v1;
            }
        }
        __syncthreads();

        // --- pointwise for 2 cells (bl, jA) and (bl, jA+1) ---
        float4 gA = *(float4*)&accbuf[bl * 36 + (jjp * 2) * 4];
        float4 gB = *(float4*)&accbuf[bl * 36 + (jjp * 2 + 1) * 4];

        {
            float gi = fsig (gxA0 + gA.x);
            float gf = fsig (gxA1 + gA.y);
            float gg = ftanh(gxA2 + gA.z);
            float go = fsig (gxA3 + gA.w);
            cA = gf * cA + gi * gg;
            hA = go * ftanh(cA);

            gi = fsig (gxB0 + gB.x);
            gf = fsig (gxB1 + gB.y);
            gg = ftanh(gxB2 + gB.z);
            go = fsig (gxB3 + gB.w);
            cB = gf * cB + gi * gg;
            hB = go * ftanh(cB);
        }

        // publish h (packed hi/lo 4B each) + outputs
        {
            __nv_bfloat16 p[2];
            p[0] = __float2bfloat16_rn(hA);
            p[1] = __float2bfloat16_rn(hB);
            *(uint32_t*)(g_hbuf_hi[(t + 1) & 1] + b * HDIM + jA) = *(uint32_t*)p;
            __nv_bfloat16 q[2];
            q[0] = __float2bfloat16_rn(hA - __bfloat162float(p[0]));
            q[1] = __float2bfloat16_rn(hB - __bfloat162float(p[1]));
            *(uint32_t*)(g_hbuf_lo[(t + 1) & 1] + b * HDIM + jA) = *(uint32_t*)q;
        }
        *(float2*)&out[(size_t)t * (BATCH * HDIM) + b * HDIM + jA] =
            make_float2(hA, hB);

        // grid barrier (R3-proven)
        __syncthreads();
        if (tid == 0) {
            __threadfence();
            asm volatile("red.release.gpu.global.add.u32 [%0], %1;"
                         :: "l"(barp), "r"(1u) : "memory");
            const unsigned target = (unsigned)(t + 1) * NBLK;
            unsigned v;
            do {
                asm volatile("ld.acquire.gpu.global.u32 %0, [%1];"
                             : "=r"(v) : "l"(barp) : "memory");
            } while (v < target);
        }
        __syncthreads();
    }

    const size_t obase = (size_t)TSTEPS * (BATCH * HDIM);
    *(float2*)&out[obase + b * HDIM + jA] = make_float2(hA, hB);
    *(float2*)&out[obase + BATCH * HDIM + b * HDIM + jA] = make_float2(cA, cB);
}

// ---------------------------------------------------------------------------
extern "C" void kernel_launch(void* const* d_in, const int* in_sizes, int n_in,
                              void* d_out, int out_size) {
    const float* inp = (const float*)d_in[0];
    const float* h0  = (const float*)d_in[1];
    const float* c0  = (const float*)d_in[2];
    const float* Wih = (const float*)d_in[3];
    const float* Whh = (const float*)d_in[4];
    const float* bih = (const float*)d_in[5];
    const float* bhh = (const float*)d_in[6];
    float* out = (float*)d_out;

    cudaFuncSetAttribute(gemm_mma, cudaFuncAttributeMaxDynamicSharedMemorySize,
                         GEMM_SMEM);
    cudaFuncSetAttribute(lstm_rec, cudaFuncAttributeMaxDynamicSharedMemorySize,
                         REC_SMEM);

    __nv_bfloat16 *ahi, *alo, *bhi, *blo;
    cudaGetSymbolAddress((void**)&ahi, g_Ahi);
    cudaGetSymbolAddress((void**)&alo, g_Alo);
    cudaGetSymbolAddress((void**)&bhi, g_Bhi);
    cudaGetSymbolAddress((void**)&blo, g_Blo);

    split_kernel<<<(MROWS * IDIM / 4 + 255) / 256, 256>>>(inp, ahi, alo,
                                                          MROWS * IDIM / 4);
    split_kernel<<<(NGATE * IDIM / 4 + 255) / 256, 256>>>(Wih, bhi, blo,
                                                          NGATE * IDIM / 4);

    dim3 gridA(NGATE / 128, MROWS / 128);
    gemm_mma<<<gridA, 256, GEMM_SMEM>>>(bih, bhh);

    init_kernel<<<(BATCH * HDIM + 255) / 256, 256>>>(h0);
    lstm_rec<<<NBLK, 128, REC_SMEM>>>(c0, Whh, out);
}

// round 14
// speedup vs baseline: 2.3728x; 1.0437x over previous
#include <cuda_runtime.h>
#include <cuda_bf16.h>
#include <cstdint>
#include <cstddef>

// LSTM layer: T=2048, B=64, I=512, H=512, fp32.
//   d_out = outputs[T,B,H] ++ h_T[B,H] ++ c_T[B,H]
// Kernel S : split fp32 -> bf16 hi/lo for inp and W_ih
// Kernel A : mma.sync split-bf16 GEMM -> g_gates (+biases) [R10-proven]
// Kernel I : reset barriers + convert h0 -> bf16 hi/lo
// Kernel B : persistent recurrence, HMMA split-bf16, CTA tile M16xN64.
//            4 independent barrier groups of 32 CTAs (batch quarters).

#define TSTEPS 2048
#define BATCH  64
#define IDIM   512
#define HDIM   512
#define NGATE  2048
#define MROWS  (TSTEPS * BATCH)
#define NBLK   128

__device__ float          g_gates[(size_t)MROWS * NGATE];   // 1 GiB
__device__ __nv_bfloat16  g_Ahi[(size_t)MROWS * IDIM];
__device__ __nv_bfloat16  g_Alo[(size_t)MROWS * IDIM];
__device__ __nv_bfloat16  g_Bhi[(size_t)NGATE * IDIM];
__device__ __nv_bfloat16  g_Blo[(size_t)NGATE * IDIM];
__device__ __nv_bfloat16  g_hbuf_hi[2][BATCH * HDIM];
__device__ __nv_bfloat16  g_hbuf_lo[2][BATCH * HDIM];
__device__ unsigned       g_bar4[4 * 32];    // 4 counters, 128B apart

// ---------------------------------------------------------------------------
// Kernel I: reset barriers + h0 -> bf16 hi/lo into buffer 0
// ---------------------------------------------------------------------------
__global__ void init_kernel(const float* __restrict__ h0) {
    int i = blockIdx.x * 256 + threadIdx.x;
    if (i < 128) g_bar4[i] = 0u;
    if (i < BATCH * HDIM) {
        float v = h0[i];
        __nv_bfloat16 hi = __float2bfloat16_rn(v);
        __nv_bfloat16 lo = __float2bfloat16_rn(v - __bfloat162float(hi));
        g_hbuf_hi[0][i] = hi;
        g_hbuf_lo[0][i] = lo;
    }
}

// ---------------------------------------------------------------------------
// Kernel S: fp32 -> (bf16 hi, bf16 lo) split, 4 elems/thread
// ---------------------------------------------------------------------------
__global__ void split_kernel(const float* __restrict__ s,
                             __nv_bfloat16* __restrict__ hi,
                             __nv_bfloat16* __restrict__ lo, int n4)
{
    int i = blockIdx.x * 256 + threadIdx.x;
    if (i >= n4) return;
    float4 v = ((const float4*)s)[i];
    float f[4] = {v.x, v.y, v.z, v.w};
    __nv_bfloat16 h[4], l[4];
#pragma unroll
    for (int k = 0; k < 4; k++) {
        h[k] = __float2bfloat16_rn(f[k]);
        l[k] = __float2bfloat16_rn(f[k] - __bfloat162float(h[k]));
    }
    *(uint2*)(hi + (size_t)i * 4) = *(uint2*)h;
    *(uint2*)(lo + (size_t)i * 4) = *(uint2*)l;
}

// ---------------------------------------------------------------------------
// shared helpers
// ---------------------------------------------------------------------------
__device__ __forceinline__ uint32_t smem_u32(const void* p) {
    uint32_t a;
    asm("{ .reg .u64 t; cvta.to.shared.u64 t, %1; cvt.u32.u64 %0, t; }"
        : "=r"(a) : "l"(p));
    return a;
}
__device__ __forceinline__ void ldsm4(uint32_t* r, uint32_t addr) {
    asm volatile("ldmatrix.sync.aligned.m8n8.x4.shared.b16 {%0,%1,%2,%3},[%4];"
                 : "=r"(r[0]), "=r"(r[1]), "=r"(r[2]), "=r"(r[3]) : "r"(addr));
}
__device__ __forceinline__ void hmma(float* d, const uint32_t* a, const uint32_t* b) {
    asm volatile("mma.sync.aligned.m16n8k16.row.col.f32.bf16.bf16.f32 "
                 "{%0,%1,%2,%3},{%4,%5,%6,%7},{%8,%9},{%0,%1,%2,%3};"
                 : "+f"(d[0]), "+f"(d[1]), "+f"(d[2]), "+f"(d[3])
                 : "r"(a[0]), "r"(a[1]), "r"(a[2]), "r"(a[3]),
                   "r"(b[0]), "r"(b[1]));
}

// ---------------------------------------------------------------------------
// Kernel A: split-bf16 mma.sync GEMM (R10-proven, unchanged)
// ---------------------------------------------------------------------------
#define STG_BYTES 40960
#define GEMM_SMEM (2 * STG_BYTES)

__global__ __launch_bounds__(256, 1)
void gemm_mma(const float* __restrict__ bih, const float* __restrict__ bhh)
{
    extern __shared__ char smem[];
    const uint32_t sbase = smem_u32(smem);

    const int tid  = threadIdx.x;
    const int wid  = tid >> 5, lane = tid & 31;
    const int wm   = wid & 3;
    const int wn   = wid >> 2;
    const int n0   = blockIdx.x * 128;
    const size_t m0 = (size_t)blockIdx.y * 128;

    const int OF_AHI = 0, OF_ALO = 10240, OF_BHI = 20480, OF_BLO = 30720;

    const int lm = lane >> 3, lr = lane & 7;
    uint32_t addrA[2], addrB[4];
#pragma unroll
    for (int mt = 0; mt < 2; mt++) {
        int row = wm * 32 + mt * 16 + (lm & 1) * 8 + lr;
        addrA[mt] = (uint32_t)(row * 80 + (lm >> 1) * 16);
    }
#pragma unroll
    for (int p = 0; p < 4; p++) {
        int row = wn * 64 + p * 16 + (lm >> 1) * 8 + lr;
        addrB[p] = (uint32_t)(row * 80 + (lm & 1) * 16);
    }

    const __nv_bfloat16* srcA_hi = g_Ahi + m0 * 512;
    const __nv_bfloat16* srcA_lo = g_Alo + m0 * 512;
    const __nv_bfloat16* srcB_hi = g_Bhi + (size_t)n0 * 512;
    const __nv_bfloat16* srcB_lo = g_Blo + (size_t)n0 * 512;

    float acc[2][8][4];
#pragma unroll
    for (int mt = 0; mt < 2; mt++)
#pragma unroll
        for (int nt = 0; nt < 8; nt++)
#pragma unroll
            for (int q = 0; q < 4; q++) acc[mt][nt][q] = 0.0f;

    auto stage = [&](int kc, int st) {
        const uint32_t sb = sbase + st * STG_BYTES;
#pragma unroll
        for (int it = 0; it < 2; it++) {
            int idx = tid + it * 256;
            int row = idx >> 2, c8 = idx & 3;
            uint32_t doff = (uint32_t)(row * 80 + c8 * 16);
            const __nv_bfloat16* sa = srcA_hi + (size_t)row * 512 + kc * 32 + c8 * 8;
            const __nv_bfloat16* sb2 = srcA_lo + (size_t)row * 512 + kc * 32 + c8 * 8;
            const __nv_bfloat16* sc = srcB_hi + (size_t)row * 512 + kc * 32 + c8 * 8;
            const __nv_bfloat16* sd = srcB_lo + (size_t)row * 512 + kc * 32 + c8 * 8;
            asm volatile("cp.async.cg.shared.global [%0],[%1],16;"
                         :: "r"(sb + OF_AHI + doff), "l"(sa));
            asm volatile("cp.async.cg.shared.global [%0],[%1],16;"
                         :: "r"(sb + OF_ALO + doff), "l"(sb2));
            asm volatile("cp.async.cg.shared.global [%0],[%1],16;"
                         :: "r"(sb + OF_BHI + doff), "l"(sc));
            asm volatile("cp.async.cg.shared.global [%0],[%1],16;"
                         :: "r"(sb + OF_BLO + doff), "l"(sd));
        }
        asm volatile("cp.async.commit_group;");
    };

    stage(0, 0);

    for (int kc = 0; kc < 16; kc++) {
        const int st = kc & 1;
        if (kc + 1 < 16) {
            stage(kc + 1, st ^ 1);
            asm volatile("cp.async.wait_group 1;");
        } else {
            asm volatile("cp.async.wait_group 0;");
        }
        __syncthreads();

        const uint32_t sb = sbase + st * STG_BYTES;
#pragma unroll
        for (int ks = 0; ks < 2; ks++) {
            const uint32_t ko = (uint32_t)(ks * 32);
            uint32_t ahi[2][4], alo[2][4], bhi[8][2], blo[8][2];
#pragma unroll
            for (int mt = 0; mt < 2; mt++) {
                ldsm4(ahi[mt], sb + OF_AHI + addrA[mt] + ko);
                ldsm4(alo[mt], sb + OF_ALO + addrA[mt] + ko);
            }
#pragma unroll
            for (int p = 0; p < 4; p++) {
                uint32_t r[4];
                ldsm4(r, sb + OF_BHI + addrB[p] + ko);
                bhi[p * 2][0] = r[0]; bhi[p * 2][1] = r[1];
                bhi[p * 2 + 1][0] = r[2]; bhi[p * 2 + 1][1] = r[3];
                ldsm4(r, sb + OF_BLO + addrB[p] + ko);
                blo[p * 2][0] = r[0]; blo[p * 2][1] = r[1];
                blo[p * 2 + 1][0] = r[2]; blo[p * 2 + 1][1] = r[3];
            }
#pragma unroll
            for (int mt = 0; mt < 2; mt++)
#pragma unroll
                for (int nt = 0; nt < 8; nt++) {
                    hmma(acc[mt][nt], ahi[mt], bhi[nt]);
                    hmma(acc[mt][nt], ahi[mt], blo[nt]);
                    hmma(acc[mt][nt], alo[mt], bhi[nt]);
                }
        }
        __syncthreads();
    }

    const int cq = (lane & 3) * 2, rq = lane >> 2;
#pragma unroll
    for (int nt = 0; nt < 8; nt++) {
        const int col = n0 + wn * 64 + nt * 8 + cq;
        float2 bsum;
        bsum.x = bih[col]     + bhh[col];
        bsum.y = bih[col + 1] + bhh[col + 1];
#pragma unroll
        for (int mt = 0; mt < 2; mt++) {
            const size_t r0 = m0 + wm * 32 + mt * 16 + rq;
            float2 v0 = make_float2(acc[mt][nt][0] + bsum.x, acc[mt][nt][1] + bsum.y);
            float2 v1 = make_float2(acc[mt][nt][2] + bsum.x, acc[mt][nt][3] + bsum.y);
            *(float2*)&g_gates[r0 * NGATE + col]       = v0;
            *(float2*)&g_gates[(r0 + 8) * NGATE + col] = v1;
        }
    }
}

// ---------------------------------------------------------------------------
// Kernel B: persistent recurrence, CTA tile M16 x N64.
// 128 CTAs = 4 batch groups x 32 j-tiles (16 j each). 128 thr, 4 warps (N16 each).
// ---------------------------------------------------------------------------
__device__ __forceinline__ float fsig(float x) {
    return __fdividef(1.0f, 1.0f + __expf(-x));
}
__device__ __forceinline__ float ftanh(float x) {
    x = fminf(fmaxf(x, -15.0f), 15.0f);
    float e = __expf(-2.0f * x);
    return __fdividef(1.0f - e, 1.0f + e);
}

#define RSTR    1040
#define OFF_WHI 0
#define OFF_WLO (64 * RSTR)              // 66560
#define OFF_HHI (2 * 64 * RSTR)          // 133120
#define OFF_HLO (OFF_HHI + 16 * RSTR)    // 149760
#define OFF_ACC (OFF_HLO + 16 * RSTR)    // 166400 ; 16 x 68 fp32 = 4352
#define REC_SMEM (OFF_ACC + 16 * 68 * 4) // 170752 -> 1 CTA/SM

__global__ __launch_bounds__(128, 1)
void lstm_rec(const float* __restrict__ c0,
              const float* __restrict__ Whh,
              float* __restrict__ out)
{
    extern __shared__ char smem[];
    const uint32_t sbase = smem_u32(smem);
    float* accbuf = (float*)(smem + OFF_ACC);

    const int tid  = threadIdx.x;
    const int cb   = blockIdx.x;
    const int grp  = cb >> 5;            // batch group 0..3
    const int b0   = grp * 16;
    const int j0   = (cb & 31) * 16;     // 16 j's per CTA
    const int wid  = tid >> 5, lane = tid & 31;

    // --- stage W_hh (split bf16 hi/lo) once: 64 rows (n = jj*4+gate) x 512 ---
#pragma unroll 8
    for (int i = 0; i < 64; i++) {
        int idx = tid + i * 128;             // 0..8191 float4 chunks
        int row = idx >> 7, c4 = idx & 127;
        int R = (row & 3) * HDIM + j0 + (row >> 2);   // gate*512 + j0 + jj
        float4 v = *(const float4*)&Whh[(size_t)R * HDIM + c4 * 4];
        float f[4] = {v.x, v.y, v.z, v.w};
        __nv_bfloat16 h[4], l[4];
#pragma unroll
        for (int q = 0; q < 4; q++) {
            h[q] = __float2bfloat16_rn(f[q]);
            l[q] = __float2bfloat16_rn(f[q] - __bfloat162float(h[q]));
        }
        *(uint2*)(smem + OFF_WHI + row * RSTR + c4 * 8) = *(uint2*)h;
        *(uint2*)(smem + OFF_WLO + row * RSTR + c4 * 8) = *(uint2*)l;
    }

    // --- per-thread cell mapping: 256 cells (16 b x 16 j), 2 adjacent-j cells ---
    const int bl  = tid & 15;
    const int jp  = tid >> 4;            // 0..7
    const int jjA = jp * 2;
    const int b   = b0 + bl;
    const int jA  = j0 + jjA;

    float cA = c0[b * HDIM + jA];
    float cB = c0[b * HDIM + jA + 1];
    float hA = 0.0f, hB = 0.0f;

    // --- ldmatrix addresses (R12-proven lane mapping; wm removed, wn=wid) ---
    const int lm = lane >> 3, lr = lane & 7;
    const uint32_t aAddr = sbase + OFF_HHI
        + (uint32_t)(((lm & 1) * 8 + lr) * RSTR + (lm >> 1) * 16);
    const uint32_t bAddr = sbase + OFF_WHI
        + (uint32_t)((wid * 16 + (lm >> 1) * 8 + lr) * RSTR + (lm & 1) * 16);
    const uint32_t LOH = OFF_HLO - OFF_HHI;   // 16640
    const uint32_t LOW = OFF_WLO - OFF_WHI;   // 66560

    unsigned long long barp =
        (unsigned long long)__cvta_generic_to_global(&g_bar4[grp * 32]);

    for (int t = 0; t < TSTEPS; t++) {
        // prefetch gx for both cells
        const float* gxp = g_gates + (size_t)(t * BATCH + b) * NGATE + jA;
        float gxA0 = __ldcs(gxp);
        float gxA1 = __ldcs(gxp + 512);
        float gxA2 = __ldcs(gxp + 1024);
        float gxA3 = __ldcs(gxp + 1536);
        float gxB0 = __ldcs(gxp + 1);
        float gxB1 = __ldcs(gxp + 513);
        float gxB2 = __ldcs(gxp + 1025);
        float gxB3 = __ldcs(gxp + 1537);

        // stage h hi/lo (16 batches x 512 bf16 each) via cp.async
        const __nv_bfloat16* shi = g_hbuf_hi[t & 1] + (size_t)b0 * HDIM;
        const __nv_bfloat16* slo = g_hbuf_lo[t & 1] + (size_t)b0 * HDIM;
#pragma unroll
        for (int i = 0; i < 8; i++) {
            int idx = tid + i * 128;         // 0..1023
            int row = idx >> 6, c = idx & 63;
            uint32_t doff = (uint32_t)(row * RSTR + c * 16);
            asm volatile("cp.async.cg.shared.global [%0],[%1],16;"
                         :: "r"(sbase + OFF_HHI + doff), "l"(shi + row * 512 + c * 8));
            asm volatile("cp.async.cg.shared.global [%0],[%1],16;"
                         :: "r"(sbase + OFF_HLO + doff), "l"(slo + row * 512 + c * 8));
        }
        asm volatile("cp.async.commit_group;");
        asm volatile("cp.async.wait_group 0;");
        __syncthreads();

        // --- HMMA mainloop: M16 x N16 per warp, K=512, 3-term split ---
        float accP[8], accQ[8];
#pragma unroll
        for (int q = 0; q < 8; q++) { accP[q] = 0.0f; accQ[q] = 0.0f; }

#pragma unroll 8
        for (int ks = 0; ks < 32; ks++) {
            const uint32_t ko = (uint32_t)(ks * 32);
            uint32_t ahi[4], alo[4], bhi[4], blo[4];
            ldsm4(ahi, aAddr + ko);
            ldsm4(alo, aAddr + LOH + ko);
            ldsm4(bhi, bAddr + ko);
            ldsm4(blo, bAddr + LOW + ko);
            hmma(accP + 0, ahi, bhi + 0);
            hmma(accP + 4, ahi, bhi + 2);
            hmma(accQ + 0, ahi, blo + 0);
            hmma(accQ + 4, ahi, blo + 2);
            hmma(accQ + 0, alo, bhi + 0);
            hmma(accQ + 4, alo, bhi + 2);
        }

        // STS acc to exchange buffer (16 rows=batch, 64 cols=n, stride 68)
        {
            const int crow = lane >> 2, ccol = (lane & 3) * 2;
#pragma unroll
            for (int nt = 0; nt < 2; nt++) {
                const int col = wid * 16 + nt * 8 + ccol;
                float2 v0 = make_float2(accP[nt * 4 + 0] + accQ[nt * 4 + 0],
                                        accP[nt * 4 + 1] + accQ[nt * 4 + 1]);
                float2 v1 = make_float2(accP[nt * 4 + 2] + accQ[nt * 4 + 2],
                                        accP[nt * 4 + 3] + accQ[nt * 4 + 3]);
                *(float2*)&accbuf[crow * 68 + col]       = v0;
                *(float2*)&accbuf[(crow + 8) * 68 + col] = v1;
            }
        }
        __syncthreads();

        // --- pointwise for cells (b, jA) and (b, jA+1) ---
        float4 gA = *(float4*)&accbuf[bl * 68 + jjA * 4];
        float4 gB = *(float4*)&accbuf[bl * 68 + jjA * 4 + 4];

        {
            float gi = fsig (gxA0 + gA.x);
            float gf = fsig (gxA1 + gA.y);
            float gg = ftanh(gxA2 + gA.z);
            float go = fsig (gxA3 + gA.w);
            cA = gf * cA + gi * gg;
            hA = go * ftanh(cA);

            gi = fsig (gxB0 + gB.x);
            gf = fsig (gxB1 + gB.y);
            gg = ftanh(gxB2 + gB.z);
            go = fsig (gxB3 + gB.w);
            cB = gf * cB + gi * gg;
            hB = go * ftanh(cB);
        }

        // publish h (packed hi/lo, 4B each) + outputs
        {
            __nv_bfloat16 p[2];
            p[0] = __float2bfloat16_rn(hA);
            p[1] = __float2bfloat16_rn(hB);
            *(uint32_t*)(g_hbuf_hi[(t + 1) & 1] + b * HDIM + jA) = *(uint32_t*)p;
            __nv_bfloat16 q[2];
            q[0] = __float2bfloat16_rn(hA - __bfloat162float(p[0]));
            q[1] = __float2bfloat16_rn(hB - __bfloat162float(p[1]));
            *(uint32_t*)(g_hbuf_lo[(t + 1) & 1] + b * HDIM + jA) = *(uint32_t*)q;
        }
        *(float2*)&out[(size_t)t * (BATCH * HDIM) + b * HDIM + jA] =
            make_float2(hA, hB);

        // per-group grid barrier (32 CTAs)
        __syncthreads();
        if (tid == 0) {
            __threadfence();
            asm volatile("red.release.gpu.global.add.u32 [%0], %1;"
                         :: "l"(barp), "r"(1u) : "memory");
            const unsigned target = (unsigned)(t + 1) * 32;
            unsigned v;
            do {
                asm volatile("ld.acquire.gpu.global.u32 %0, [%1];"
                             : "=r"(v) : "l"(barp) : "memory");
            } while (v < target);
        }
        __syncthreads();
    }

    const size_t obase = (size_t)TSTEPS * (BATCH * HDIM);
    *(float2*)&out[obase + b * HDIM + jA] = make_float2(hA, hB);
    *(float2*)&out[obase + BATCH * HDIM + b * HDIM + jA] = make_float2(cA, cB);
}

// ---------------------------------------------------------------------------
extern "C" void kernel_launch(void* const* d_in, const int* in_sizes, int n_in,
                              void* d_out, int out_size) {
    const float* inp = (const float*)d_in[0];
    const float* h0  = (const float*)d_in[1];
    const float* c0  = (const float*)d_in[2];
    const float* Wih = (const float*)d_in[3];
    const float* Whh = (const float*)d_in[4];
    const float* bih = (const float*)d_in[5];
    const float* bhh = (const float*)d_in[6];
    float* out = (float*)d_out;

    cudaFuncSetAttribute(gemm_mma, cudaFuncAttributeMaxDynamicSharedMemorySize,
                         GEMM_SMEM);
    cudaFuncSetAttribute(lstm_rec, cudaFuncAttributeMaxDynamicSharedMemorySize,
                         REC_SMEM);

    __nv_bfloat16 *ahi, *alo, *bhi, *blo;
    cudaGetSymbolAddress((void**)&ahi, g_Ahi);
    cudaGetSymbolAddress((void**)&alo, g_Alo);
    cudaGetSymbolAddress((void**)&bhi, g_Bhi);
    cudaGetSymbolAddress((void**)&blo, g_Blo);

    split_kernel<<<(MROWS * IDIM / 4 + 255) / 256, 256>>>(inp, ahi, alo,
                                                          MROWS * IDIM / 4);
    split_kernel<<<(NGATE * IDIM / 4 + 255) / 256, 256>>>(Wih, bhi, blo,
                                                          NGATE * IDIM / 4);

    dim3 gridA(NGATE / 128, MROWS / 128);
    gemm_mma<<<gridA, 256, GEMM_SMEM>>>(bih, bhh);

    init_kernel<<<(BATCH * HDIM + 255) / 256, 256>>>(h0);
    lstm_rec<<<NBLK, 128, REC_SMEM>>>(c0, Whh, out);
}

// round 15
// speedup vs baseline: 2.3844x; 1.0049x over previous
#include <cuda_runtime.h>
#include <cuda_bf16.h>
#include <cstdint>
#include <cstddef>

// LSTM layer: T=2048, B=64, I=512, H=512, fp32.
//   d_out = outputs[T,B,H] ++ h_T[B,H] ++ c_T[B,H]
// Kernel S : split fp32 -> bf16 hi/lo for inp and W_ih
// Kernel A : mma.sync split-bf16 GEMM -> g_gates (+biases) [R10-proven]
// Kernel I : reset barriers + convert h0 -> bf16 hi/lo
// Kernel B : persistent recurrence, HMMA split-bf16, CTA tile M16xN64,
//            4 barrier groups of 32 CTAs, hi/lo staged as separate
//            cp.async groups (lo copy overlapped with hi-term HMMAs),
//            out-stores + gx prefetch moved off the critical path.

#define TSTEPS 2048
#define BATCH  64
#define IDIM   512
#define HDIM   512
#define NGATE  2048
#define MROWS  (TSTEPS * BATCH)
#define NBLK   128

__device__ float          g_gates[(size_t)MROWS * NGATE];   // 1 GiB
__device__ __nv_bfloat16  g_Ahi[(size_t)MROWS * IDIM];
__device__ __nv_bfloat16  g_Alo[(size_t)MROWS * IDIM];
__device__ __nv_bfloat16  g_Bhi[(size_t)NGATE * IDIM];
__device__ __nv_bfloat16  g_Blo[(size_t)NGATE * IDIM];
__device__ __nv_bfloat16  g_hbuf_hi[2][BATCH * HDIM];
__device__ __nv_bfloat16  g_hbuf_lo[2][BATCH * HDIM];
__device__ unsigned       g_bar4[4 * 32];    // 4 counters, 128B apart

// ---------------------------------------------------------------------------
// Kernel I: reset barriers + h0 -> bf16 hi/lo into buffer 0
// ---------------------------------------------------------------------------
__global__ void init_kernel(const float* __restrict__ h0) {
    int i = blockIdx.x * 256 + threadIdx.x;
    if (i < 128) g_bar4[i] = 0u;
    if (i < BATCH * HDIM) {
        float v = h0[i];
        __nv_bfloat16 hi = __float2bfloat16_rn(v);
        __nv_bfloat16 lo = __float2bfloat16_rn(v - __bfloat162float(hi));
        g_hbuf_hi[0][i] = hi;
        g_hbuf_lo[0][i] = lo;
    }
}

// ---------------------------------------------------------------------------
// Kernel S: fp32 -> (bf16 hi, bf16 lo) split, 4 elems/thread
// ---------------------------------------------------------------------------
__global__ void split_kernel(const float* __restrict__ s,
                             __nv_bfloat16* __restrict__ hi,
                             __nv_bfloat16* __restrict__ lo, int n4)
{
    int i = blockIdx.x * 256 + threadIdx.x;
    if (i >= n4) return;
    float4 v = ((const float4*)s)[i];
    float f[4] = {v.x, v.y, v.z, v.w};
    __nv_bfloat16 h[4], l[4];
#pragma unroll
    for (int k = 0; k < 4; k++) {
        h[k] = __float2bfloat16_rn(f[k]);
        l[k] = __float2bfloat16_rn(f[k] - __bfloat162float(h[k]));
    }
    *(uint2*)(hi + (size_t)i * 4) = *(uint2*)h;
    *(uint2*)(lo + (size_t)i * 4) = *(uint2*)l;
}

// ---------------------------------------------------------------------------
// shared helpers
// ---------------------------------------------------------------------------
__device__ __forceinline__ uint32_t smem_u32(const void* p) {
    uint32_t a;
    asm("{ .reg .u64 t; cvta.to.shared.u64 t, %1; cvt.u32.u64 %0, t; }"
        : "=r"(a) : "l"(p));
    return a;
}
__device__ __forceinline__ void ldsm4(uint32_t* r, uint32_t addr) {
    asm volatile("ldmatrix.sync.aligned.m8n8.x4.shared.b16 {%0,%1,%2,%3},[%4];"
                 : "=r"(r[0]), "=r"(r[1]), "=r"(r[2]), "=r"(r[3]) : "r"(addr));
}
__device__ __forceinline__ void hmma(float* d, const uint32_t* a, const uint32_t* b) {
    asm volatile("mma.sync.aligned.m16n8k16.row.col.f32.bf16.bf16.f32 "
                 "{%0,%1,%2,%3},{%4,%5,%6,%7},{%8,%9},{%0,%1,%2,%3};"
                 : "+f"(d[0]), "+f"(d[1]), "+f"(d[2]), "+f"(d[3])
                 : "r"(a[0]), "r"(a[1]), "r"(a[2]), "r"(a[3]),
                   "r"(b[0]), "r"(b[1]));
}

// ---------------------------------------------------------------------------
// Kernel A: split-bf16 mma.sync GEMM (R10-proven, unchanged)
// ---------------------------------------------------------------------------
#define STG_BYTES 40960
#define GEMM_SMEM (2 * STG_BYTES)

__global__ __launch_bounds__(256, 1)
void gemm_mma(const float* __restrict__ bih, const float* __restrict__ bhh)
{
    extern __shared__ char smem[];
    const uint32_t sbase = smem_u32(smem);

    const int tid  = threadIdx.x;
    const int wid  = tid >> 5, lane = tid & 31;
    const int wm   = wid & 3;
    const int wn   = wid >> 2;
    const int n0   = blockIdx.x * 128;
    const size_t m0 = (size_t)blockIdx.y * 128;

    const int OF_AHI = 0, OF_ALO = 10240, OF_BHI = 20480, OF_BLO = 30720;

    const int lm = lane >> 3, lr = lane & 7;
    uint32_t addrA[2], addrB[4];
#pragma unroll
    for (int mt = 0; mt < 2; mt++) {
        int row = wm * 32 + mt * 16 + (lm & 1) * 8 + lr;
        addrA[mt] = (uint32_t)(row * 80 + (lm >> 1) * 16);
    }
#pragma unroll
    for (int p = 0; p < 4; p++) {
        int row = wn * 64 + p * 16 + (lm >> 1) * 8 + lr;
        addrB[p] = (uint32_t)(row * 80 + (lm & 1) * 16);
    }

    const __nv_bfloat16* srcA_hi = g_Ahi + m0 * 512;
    const __nv_bfloat16* srcA_lo = g_Alo + m0 * 512;
    const __nv_bfloat16* srcB_hi = g_Bhi + (size_t)n0 * 512;
    const __nv_bfloat16* srcB_lo = g_Blo + (size_t)n0 * 512;

    float acc[2][8][4];
#pragma unroll
    for (int mt = 0; mt < 2; mt++)
#pragma unroll
        for (int nt = 0; nt < 8; nt++)
#pragma unroll
            for (int q = 0; q < 4; q++) acc[mt][nt][q] = 0.0f;

    auto stage = [&](int kc, int st) {
        const uint32_t sb = sbase + st * STG_BYTES;
#pragma unroll
        for (int it = 0; it < 2; it++) {
            int idx = tid + it * 256;
            int row = idx >> 2, c8 = idx & 3;
            uint32_t doff = (uint32_t)(row * 80 + c8 * 16);
            const __nv_bfloat16* sa = srcA_hi + (size_t)row * 512 + kc * 32 + c8 * 8;
            const __nv_bfloat16* sb2 = srcA_lo + (size_t)row * 512 + kc * 32 + c8 * 8;
            const __nv_bfloat16* sc = srcB_hi + (size_t)row * 512 + kc * 32 + c8 * 8;
            const __nv_bfloat16* sd = srcB_lo + (size_t)row * 512 + kc * 32 + c8 * 8;
            asm volatile("cp.async.cg.shared.global [%0],[%1],16;"
                         :: "r"(sb + OF_AHI + doff), "l"(sa));
            asm volatile("cp.async.cg.shared.global [%0],[%1],16;"
                         :: "r"(sb + OF_ALO + doff), "l"(sb2));
            asm volatile("cp.async.cg.shared.global [%0],[%1],16;"
                         :: "r"(sb + OF_BHI + doff), "l"(sc));
            asm volatile("cp.async.cg.shared.global [%0],[%1],16;"
                         :: "r"(sb + OF_BLO + doff), "l"(sd));
        }
        asm volatile("cp.async.commit_group;");
    };

    stage(0, 0);

    for (int kc = 0; kc < 16; kc++) {
        const int st = kc & 1;
        if (kc + 1 < 16) {
            stage(kc + 1, st ^ 1);
            asm volatile("cp.async.wait_group 1;");
        } else {
            asm volatile("cp.async.wait_group 0;");
        }
        __syncthreads();

        const uint32_t sb = sbase + st * STG_BYTES;
#pragma unroll
        for (int ks = 0; ks < 2; ks++) {
            const uint32_t ko = (uint32_t)(ks * 32);
            uint32_t ahi[2][4], alo[2][4], bhi[8][2], blo[8][2];
#pragma unroll
            for (int mt = 0; mt < 2; mt++) {
                ldsm4(ahi[mt], sb + OF_AHI + addrA[mt] + ko);
                ldsm4(alo[mt], sb + OF_ALO + addrA[mt] + ko);
            }
#pragma unroll
            for (int p = 0; p < 4; p++) {
                uint32_t r[4];
                ldsm4(r, sb + OF_BHI + addrB[p] + ko);
                bhi[p * 2][0] = r[0]; bhi[p * 2][1] = r[1];
                bhi[p * 2 + 1][0] = r[2]; bhi[p * 2 + 1][1] = r[3];
                ldsm4(r, sb + OF_BLO + addrB[p] + ko);
                blo[p * 2][0] = r[0]; blo[p * 2][1] = r[1];
                blo[p * 2 + 1][0] = r[2]; blo[p * 2 + 1][1] = r[3];
            }
#pragma unroll
            for (int mt = 0; mt < 2; mt++)
#pragma unroll
                for (int nt = 0; nt < 8; nt++) {
                    hmma(acc[mt][nt], ahi[mt], bhi[nt]);
                    hmma(acc[mt][nt], ahi[mt], blo[nt]);
                    hmma(acc[mt][nt], alo[mt], bhi[nt]);
                }
        }
        __syncthreads();
    }

    const int cq = (lane & 3) * 2, rq = lane >> 2;
#pragma unroll
    for (int nt = 0; nt < 8; nt++) {
        const int col = n0 + wn * 64 + nt * 8 + cq;
        float2 bsum;
        bsum.x = bih[col]     + bhh[col];
        bsum.y = bih[col + 1] + bhh[col + 1];
#pragma unroll
        for (int mt = 0; mt < 2; mt++) {
            const size_t r0 = m0 + wm * 32 + mt * 16 + rq;
            float2 v0 = make_float2(acc[mt][nt][0] + bsum.x, acc[mt][nt][1] + bsum.y);
            float2 v1 = make_float2(acc[mt][nt][2] + bsum.x, acc[mt][nt][3] + bsum.y);
            *(float2*)&g_gates[r0 * NGATE + col]       = v0;
            *(float2*)&g_gates[(r0 + 8) * NGATE + col] = v1;
        }
    }
}

// ---------------------------------------------------------------------------
// Kernel B: persistent recurrence, CTA tile M16 x N64.
// 128 CTAs = 4 batch groups x 32 j-tiles. 128 thr, 4 warps (N16 each).
// ---------------------------------------------------------------------------
__device__ __forceinline__ float fsig(float x) {
    return __fdividef(1.0f, 1.0f + __expf(-x));
}
__device__ __forceinline__ float ftanh(float x) {
    x = fminf(fmaxf(x, -15.0f), 15.0f);
    float e = __expf(-2.0f * x);
    return __fdividef(1.0f - e, 1.0f + e);
}

#define RSTR    1040
#define OFF_WHI 0
#define OFF_WLO (64 * RSTR)              // 66560
#define OFF_HHI (2 * 64 * RSTR)          // 133120
#define OFF_HLO (OFF_HHI + 16 * RSTR)    // 149760
#define OFF_ACC (OFF_HLO + 16 * RSTR)    // 166400 ; 16 x 68 fp32 = 4352
#define REC_SMEM (OFF_ACC + 16 * 68 * 4) // 170752 -> 1 CTA/SM

__global__ __launch_bounds__(128, 1)
void lstm_rec(const float* __restrict__ c0,
              const float* __restrict__ Whh,
              float* __restrict__ out)
{
    extern __shared__ char smem[];
    const uint32_t sbase = smem_u32(smem);
    float* accbuf = (float*)(smem + OFF_ACC);

    const int tid  = threadIdx.x;
    const int cb   = blockIdx.x;
    const int grp  = cb >> 5;            // batch group 0..3
    const int b0   = grp * 16;
    const int j0   = (cb & 31) * 16;     // 16 j's per CTA
    const int wid  = tid >> 5, lane = tid & 31;

    // --- stage W_hh (split bf16 hi/lo) once: 64 rows (n = jj*4+gate) x 512 ---
#pragma unroll 8
    for (int i = 0; i < 64; i++) {
        int idx = tid + i * 128;
        int row = idx >> 7, c4 = idx & 127;
        int R = (row & 3) * HDIM + j0 + (row >> 2);   // gate*512 + j0 + jj
        float4 v = *(const float4*)&Whh[(size_t)R * HDIM + c4 * 4];
        float f[4] = {v.x, v.y, v.z, v.w};
        __nv_bfloat16 h[4], l[4];
#pragma unroll
        for (int q = 0; q < 4; q++) {
            h[q] = __float2bfloat16_rn(f[q]);
            l[q] = __float2bfloat16_rn(f[q] - __bfloat162float(h[q]));
        }
        *(uint2*)(smem + OFF_WHI + row * RSTR + c4 * 8) = *(uint2*)h;
        *(uint2*)(smem + OFF_WLO + row * RSTR + c4 * 8) = *(uint2*)l;
    }

    // --- per-thread cell mapping: 2 adjacent-j cells ---
    const int bl  = tid & 15;
    const int jp  = tid >> 4;            // 0..7
    const int jjA = jp * 2;
    const int b   = b0 + bl;
    const int jA  = j0 + jjA;

    float cA = c0[b * HDIM + jA];
    float cB = c0[b * HDIM + jA + 1];
    float hA = 0.0f, hB = 0.0f;

    // --- ldmatrix addresses (proven lane mapping) ---
    const int lm = lane >> 3, lr = lane & 7;
    const uint32_t aAddr = sbase + OFF_HHI
        + (uint32_t)(((lm & 1) * 8 + lr) * RSTR + (lm >> 1) * 16);
    const uint32_t bAddr = sbase + OFF_WHI
        + (uint32_t)((wid * 16 + (lm >> 1) * 8 + lr) * RSTR + (lm & 1) * 16);
    const uint32_t LOH = OFF_HLO - OFF_HHI;
    const uint32_t LOW = OFF_WLO - OFF_WHI;

    unsigned long long barp =
        (unsigned long long)__cvta_generic_to_global(&g_bar4[grp * 32]);

    // gx double buffer: current in gxc[], next prefetched into gxn[]
    float gxc[8], gxn[8];
    {
        const float* gxp = g_gates + (size_t)(0 * BATCH + b) * NGATE + jA;
        gxc[0] = __ldcs(gxp);        gxc[1] = __ldcs(gxp + 512);
        gxc[2] = __ldcs(gxp + 1024); gxc[3] = __ldcs(gxp + 1536);
        gxc[4] = __ldcs(gxp + 1);    gxc[5] = __ldcs(gxp + 513);
        gxc[6] = __ldcs(gxp + 1025); gxc[7] = __ldcs(gxp + 1537);
    }

    for (int t = 0; t < TSTEPS; t++) {
        // stage h hi (group 0) then lo (group 1) as separate cp.async groups
        const __nv_bfloat16* shi = g_hbuf_hi[t & 1] + (size_t)b0 * HDIM;
        const __nv_bfloat16* slo = g_hbuf_lo[t & 1] + (size_t)b0 * HDIM;
#pragma unroll
        for (int i = 0; i < 8; i++) {
            int idx = tid + i * 128;
            int row = idx >> 6, c = idx & 63;
            uint32_t doff = (uint32_t)(row * RSTR + c * 16);
            asm volatile("cp.async.cg.shared.global [%0],[%1],16;"
                         :: "r"(sbase + OFF_HHI + doff), "l"(shi + row * 512 + c * 8));
        }
        asm volatile("cp.async.commit_group;");
#pragma unroll
        for (int i = 0; i < 8; i++) {
            int idx = tid + i * 128;
            int row = idx >> 6, c = idx & 63;
            uint32_t doff = (uint32_t)(row * RSTR + c * 16);
            asm volatile("cp.async.cg.shared.global [%0],[%1],16;"
                         :: "r"(sbase + OFF_HLO + doff), "l"(slo + row * 512 + c * 8));
        }
        asm volatile("cp.async.commit_group;");

        asm volatile("cp.async.wait_group 1;");   // hi ready; lo in flight
        __syncthreads();

        float accP[8], accQ[8];
#pragma unroll
        for (int q = 0; q < 8; q++) { accP[q] = 0.0f; accQ[q] = 0.0f; }

        // loop1: terms needing only h-hi (lo copy overlaps this)
#pragma unroll 8
        for (int ks = 0; ks < 32; ks++) {
            const uint32_t ko = (uint32_t)(ks * 32);
            uint32_t ahi[4], bhi[4], blo[4];
            ldsm4(ahi, aAddr + ko);
            ldsm4(bhi, bAddr + ko);
            ldsm4(blo, bAddr + LOW + ko);
            hmma(accP + 0, ahi, bhi + 0);
            hmma(accP + 4, ahi, bhi + 2);
            hmma(accQ + 0, ahi, blo + 0);
            hmma(accQ + 4, ahi, blo + 2);
        }

        asm volatile("cp.async.wait_group 0;");   // lo ready (likely already)
        __syncthreads();

        // loop2: alo x Whi term
#pragma unroll 8
        for (int ks = 0; ks < 32; ks++) {
            const uint32_t ko = (uint32_t)(ks * 32);
            uint32_t alo[4], bhi[4];
            ldsm4(alo, aAddr + LOH + ko);
            ldsm4(bhi, bAddr + ko);
            hmma(accQ + 0, alo, bhi + 0);
            hmma(accQ + 4, alo, bhi + 2);
        }

        // STS acc to exchange buffer (16 rows=batch, 64 cols=n, stride 68)
        {
            const int crow = lane >> 2, ccol = (lane & 3) * 2;
#pragma unroll
            for (int nt = 0; nt < 2; nt++) {
                const int col = wid * 16 + nt * 8 + ccol;
                float2 v0 = make_float2(accP[nt * 4 + 0] + accQ[nt * 4 + 0],
                                        accP[nt * 4 + 1] + accQ[nt * 4 + 1]);
                float2 v1 = make_float2(accP[nt * 4 + 2] + accQ[nt * 4 + 2],
                                        accP[nt * 4 + 3] + accQ[nt * 4 + 3]);
                *(float2*)&accbuf[crow * 68 + col]       = v0;
                *(float2*)&accbuf[(crow + 8) * 68 + col] = v1;
            }
        }
        __syncthreads();

        // --- pointwise for cells (b, jA) and (b, jA+1) ---
        float4 gA = *(float4*)&accbuf[bl * 68 + jjA * 4];
        float4 gB = *(float4*)&accbuf[bl * 68 + jjA * 4 + 4];

        {
            float gi = fsig (gxc[0] + gA.x);
            float gf = fsig (gxc[1] + gA.y);
            float gg = ftanh(gxc[2] + gA.z);
            float go = fsig (gxc[3] + gA.w);
            cA = gf * cA + gi * gg;
            hA = go * ftanh(cA);

            gi = fsig (gxc[4] + gB.x);
            gf = fsig (gxc[5] + gB.y);
            gg = ftanh(gxc[6] + gB.z);
            go = fsig (gxc[7] + gB.w);
            cB = gf * cB + gi * gg;
            hB = go * ftanh(cB);
        }

        // publish h (packed hi/lo, 4B each) -- critical path
        {
            __nv_bfloat16 p[2];
            p[0] = __float2bfloat16_rn(hA);
            p[1] = __float2bfloat16_rn(hB);
            *(uint32_t*)(g_hbuf_hi[(t + 1) & 1] + b * HDIM + jA) = *(uint32_t*)p;
            __nv_bfloat16 q[2];
            q[0] = __float2bfloat16_rn(hA - __bfloat162float(p[0]));
            q[1] = __float2bfloat16_rn(hB - __bfloat162float(p[1]));
            *(uint32_t*)(g_hbuf_lo[(t + 1) & 1] + b * HDIM + jA) = *(uint32_t*)q;
        }
        __syncthreads();
        if (tid == 0) {
            __threadfence();
            asm volatile("red.release.gpu.global.add.u32 [%0], %1;"
                         :: "l"(barp), "r"(1u) : "memory");
        }

        // off-critical-path: outputs for this step + gx prefetch for t+1
        *(float2*)&out[(size_t)t * (BATCH * HDIM) + b * HDIM + jA] =
            make_float2(hA, hB);
        {
            int tn = (t + 1 < TSTEPS) ? (t + 1) : t;
            const float* gxp = g_gates + (size_t)(tn * BATCH + b) * NGATE + jA;
            gxn[0] = __ldcs(gxp);        gxn[1] = __ldcs(gxp + 512);
            gxn[2] = __ldcs(gxp + 1024); gxn[3] = __ldcs(gxp + 1536);
            gxn[4] = __ldcs(gxp + 1);    gxn[5] = __ldcs(gxp + 513);
            gxn[6] = __ldcs(gxp + 1025); gxn[7] = __ldcs(gxp + 1537);
        }

        if (tid == 0) {
            const unsigned target = (unsigned)(t + 1) * 32;
            unsigned v;
            do {
                asm volatile("ld.acquire.gpu.global.u32 %0, [%1];"
                             : "=r"(v) : "l"(barp) : "memory");
            } while (v < target);
        }
        __syncthreads();

#pragma unroll
        for (int q = 0; q < 8; q++) gxc[q] = gxn[q];
    }

    const size_t obase = (size_t)TSTEPS * (BATCH * HDIM);
    *(float2*)&out[obase + b * HDIM + jA] = make_float2(hA, hB);
    *(float2*)&out[obase + BATCH * HDIM + b * HDIM + jA] = make_float2(cA, cB);
}

// ---------------------------------------------------------------------------
extern "C" void kernel_launch(void* const* d_in, const int* in_sizes, int n_in,
                              void* d_out, int out_size) {
    const float* inp = (const float*)d_in[0];
    const float* h0  = (const float*)d_in[1];
    const float* c0  = (const float*)d_in[2];
    const float* Wih = (const float*)d_in[3];
    const float* Whh = (const float*)d_in[4];
    const float* bih = (const float*)d_in[5];
    const float* bhh = (const float*)d_in[6];
    float* out = (float*)d_out;

    cudaFuncSetAttribute(gemm_mma, cudaFuncAttributeMaxDynamicSharedMemorySize,
                         GEMM_SMEM);
    cudaFuncSetAttribute(lstm_rec, cudaFuncAttributeMaxDynamicSharedMemorySize,
                         REC_SMEM);

    __nv_bfloat16 *ahi, *alo, *bhi, *blo;
    cudaGetSymbolAddress((void**)&ahi, g_Ahi);
    cudaGetSymbolAddress((void**)&alo, g_Alo);
    cudaGetSymbolAddress((void**)&bhi, g_Bhi);
    cudaGetSymbolAddress((void**)&blo, g_Blo);

    split_kernel<<<(MROWS * IDIM / 4 + 255) / 256, 256>>>(inp, ahi, alo,
                                                          MROWS * IDIM / 4);
    split_kernel<<<(NGATE * IDIM / 4 + 255) / 256, 256>>>(Wih, bhi, blo,
                                                          NGATE * IDIM / 4);

    dim3 gridA(NGATE / 128, MROWS / 128);
    gemm_mma<<<gridA, 256, GEMM_SMEM>>>(bih, bhh);

    init_kernel<<<(BATCH * HDIM + 255) / 256, 256>>>(h0);
    lstm_rec<<<NBLK, 128, REC_SMEM>>>(c0, Whh, out);
}

// round 16
// speedup vs baseline: 2.5442x; 1.0670x over previous
#include <cuda_runtime.h>
#include <cuda_bf16.h>
#include <cstdint>
#include <cstddef>

// LSTM layer: T=2048, B=64, I=512, H=512, fp32.
//   d_out = outputs[T,B,H] ++ h_T[B,H] ++ c_T[B,H]
// Kernel S : split fp32 -> bf16 hi/lo for inp and W_ih
// Kernel A : mma.sync split-bf16 GEMM -> g_gates (+biases) [R10-proven]
// Kernel I : reset barriers + convert h0 -> bf16 hi/lo
// Kernel B : persistent recurrence, HMMA split-bf16, CTA tile M16xN64,
//            4 barrier groups of 32 CTAs. R16: shfl-based gate exchange
//            (no accbuf / no epilogue syncthreads), release-only arrive.

#define TSTEPS 2048
#define BATCH  64
#define IDIM   512
#define HDIM   512
#define NGATE  2048
#define MROWS  (TSTEPS * BATCH)
#define NBLK   128

__device__ float          g_gates[(size_t)MROWS * NGATE];   // 1 GiB
__device__ __nv_bfloat16  g_Ahi[(size_t)MROWS * IDIM];
__device__ __nv_bfloat16  g_Alo[(size_t)MROWS * IDIM];
__device__ __nv_bfloat16  g_Bhi[(size_t)NGATE * IDIM];
__device__ __nv_bfloat16  g_Blo[(size_t)NGATE * IDIM];
__device__ __nv_bfloat16  g_hbuf_hi[2][BATCH * HDIM];
__device__ __nv_bfloat16  g_hbuf_lo[2][BATCH * HDIM];
__device__ unsigned       g_bar4[4 * 32];    // 4 counters, 128B apart

// ---------------------------------------------------------------------------
// Kernel I: reset barriers + h0 -> bf16 hi/lo into buffer 0
// ---------------------------------------------------------------------------
__global__ void init_kernel(const float* __restrict__ h0) {
    int i = blockIdx.x * 256 + threadIdx.x;
    if (i < 128) g_bar4[i] = 0u;
    if (i < BATCH * HDIM) {
        float v = h0[i];
        __nv_bfloat16 hi = __float2bfloat16_rn(v);
        __nv_bfloat16 lo = __float2bfloat16_rn(v - __bfloat162float(hi));
        g_hbuf_hi[0][i] = hi;
        g_hbuf_lo[0][i] = lo;
    }
}

// ---------------------------------------------------------------------------
// Kernel S: fp32 -> (bf16 hi, bf16 lo) split, 4 elems/thread
// ---------------------------------------------------------------------------
__global__ void split_kernel(const float* __restrict__ s,
                             __nv_bfloat16* __restrict__ hi,
                             __nv_bfloat16* __restrict__ lo, int n4)
{
    int i = blockIdx.x * 256 + threadIdx.x;
    if (i >= n4) return;
    float4 v = ((const float4*)s)[i];
    float f[4] = {v.x, v.y, v.z, v.w};
    __nv_bfloat16 h[4], l[4];
#pragma unroll
    for (int k = 0; k < 4; k++) {
        h[k] = __float2bfloat16_rn(f[k]);
        l[k] = __float2bfloat16_rn(f[k] - __bfloat162float(h[k]));
    }
    *(uint2*)(hi + (size_t)i * 4) = *(uint2*)h;
    *(uint2*)(lo + (size_t)i * 4) = *(uint2*)l;
}

// ---------------------------------------------------------------------------
// shared helpers
// ---------------------------------------------------------------------------
__device__ __forceinline__ uint32_t smem_u32(const void* p) {
    uint32_t a;
    asm("{ .reg .u64 t; cvta.to.shared.u64 t, %1; cvt.u32.u64 %0, t; }"
        : "=r"(a) : "l"(p));
    return a;
}
__device__ __forceinline__ void ldsm4(uint32_t* r, uint32_t addr) {
    asm volatile("ldmatrix.sync.aligned.m8n8.x4.shared.b16 {%0,%1,%2,%3},[%4];"
                 : "=r"(r[0]), "=r"(r[1]), "=r"(r[2]), "=r"(r[3]) : "r"(addr));
}
__device__ __forceinline__ void hmma(float* d, const uint32_t* a, const uint32_t* b) {
    asm volatile("mma.sync.aligned.m16n8k16.row.col.f32.bf16.bf16.f32 "
                 "{%0,%1,%2,%3},{%4,%5,%6,%7},{%8,%9},{%0,%1,%2,%3};"
                 : "+f"(d[0]), "+f"(d[1]), "+f"(d[2]), "+f"(d[3])
                 : "r"(a[0]), "r"(a[1]), "r"(a[2]), "r"(a[3]),
                   "r"(b[0]), "r"(b[1]));
}

// ---------------------------------------------------------------------------
// Kernel A: split-bf16 mma.sync GEMM (R10-proven, unchanged)
// ---------------------------------------------------------------------------
#define STG_BYTES 40960
#define GEMM_SMEM (2 * STG_BYTES)

__global__ __launch_bounds__(256, 1)
void gemm_mma(const float* __restrict__ bih, const float* __restrict__ bhh)
{
    extern __shared__ char smem[];
    const uint32_t sbase = smem_u32(smem);

    const int tid  = threadIdx.x;
    const int wid  = tid >> 5, lane = tid & 31;
    const int wm   = wid & 3;
    const int wn   = wid >> 2;
    const int n0   = blockIdx.x * 128;
    const size_t m0 = (size_t)blockIdx.y * 128;

    const int OF_AHI = 0, OF_ALO = 10240, OF_BHI = 20480, OF_BLO = 30720;

    const int lm = lane >> 3, lr = lane & 7;
    uint32_t addrA[2], addrB[4];
#pragma unroll
    for (int mt = 0; mt < 2; mt++) {
        int row = wm * 32 + mt * 16 + (lm & 1) * 8 + lr;
        addrA[mt] = (uint32_t)(row * 80 + (lm >> 1) * 16);
    }
#pragma unroll
    for (int p = 0; p < 4; p++) {
        int row = wn * 64 + p * 16 + (lm >> 1) * 8 + lr;
        addrB[p] = (uint32_t)(row * 80 + (lm & 1) * 16);
    }

    const __nv_bfloat16* srcA_hi = g_Ahi + m0 * 512;
    const __nv_bfloat16* srcA_lo = g_Alo + m0 * 512;
    const __nv_bfloat16* srcB_hi = g_Bhi + (size_t)n0 * 512;
    const __nv_bfloat16* srcB_lo = g_Blo + (size_t)n0 * 512;

    float acc[2][8][4];
#pragma unroll
    for (int mt = 0; mt < 2; mt++)
#pragma unroll
        for (int nt = 0; nt < 8; nt++)
#pragma unroll
            for (int q = 0; q < 4; q++) acc[mt][nt][q] = 0.0f;

    auto stage = [&](int kc, int st) {
        const uint32_t sb = sbase + st * STG_BYTES;
#pragma unroll
        for (int it = 0; it < 2; it++) {
            int idx = tid + it * 256;
            int row = idx >> 2, c8 = idx & 3;
            uint32_t doff = (uint32_t)(row * 80 + c8 * 16);
            const __nv_bfloat16* sa = srcA_hi + (size_t)row * 512 + kc * 32 + c8 * 8;
            const __nv_bfloat16* sb2 = srcA_lo + (size_t)row * 512 + kc * 32 + c8 * 8;
            const __nv_bfloat16* sc = srcB_hi + (size_t)row * 512 + kc * 32 + c8 * 8;
            const __nv_bfloat16* sd = srcB_lo + (size_t)row * 512 + kc * 32 + c8 * 8;
            asm volatile("cp.async.cg.shared.global [%0],[%1],16;"
                         :: "r"(sb + OF_AHI + doff), "l"(sa));
            asm volatile("cp.async.cg.shared.global [%0],[%1],16;"
                         :: "r"(sb + OF_ALO + doff), "l"(sb2));
            asm volatile("cp.async.cg.shared.global [%0],[%1],16;"
                         :: "r"(sb + OF_BHI + doff), "l"(sc));
            asm volatile("cp.async.cg.shared.global [%0],[%1],16;"
                         :: "r"(sb + OF_BLO + doff), "l"(sd));
        }
        asm volatile("cp.async.commit_group;");
    };

    stage(0, 0);

    for (int kc = 0; kc < 16; kc++) {
        const int st = kc & 1;
        if (kc + 1 < 16) {
            stage(kc + 1, st ^ 1);
            asm volatile("cp.async.wait_group 1;");
        } else {
            asm volatile("cp.async.wait_group 0;");
        }
        __syncthreads();

        const uint32_t sb = sbase + st * STG_BYTES;
#pragma unroll
        for (int ks = 0; ks < 2; ks++) {
            const uint32_t ko = (uint32_t)(ks * 32);
            uint32_t ahi[2][4], alo[2][4], bhi[8][2], blo[8][2];
#pragma unroll
            for (int mt = 0; mt < 2; mt++) {
                ldsm4(ahi[mt], sb + OF_AHI + addrA[mt] + ko);
                ldsm4(alo[mt], sb + OF_ALO + addrA[mt] + ko);
            }
#pragma unroll
            for (int p = 0; p < 4; p++) {
                uint32_t r[4];
                ldsm4(r, sb + OF_BHI + addrB[p] + ko);
                bhi[p * 2][0] = r[0]; bhi[p * 2][1] = r[1];
                bhi[p * 2 + 1][0] = r[2]; bhi[p * 2 + 1][1] = r[3];
                ldsm4(r, sb + OF_BLO + addrB[p] + ko);
                blo[p * 2][0] = r[0]; blo[p * 2][1] = r[1];
                blo[p * 2 + 1][0] = r[2]; blo[p * 2 + 1][1] = r[3];
            }
#pragma unroll
            for (int mt = 0; mt < 2; mt++)
#pragma unroll
                for (int nt = 0; nt < 8; nt++) {
                    hmma(acc[mt][nt], ahi[mt], bhi[nt]);
                    hmma(acc[mt][nt], ahi[mt], blo[nt]);
                    hmma(acc[mt][nt], alo[mt], bhi[nt]);
                }
        }
        __syncthreads();
    }

    const int cq = (lane & 3) * 2, rq = lane >> 2;
#pragma unroll
    for (int nt = 0; nt < 8; nt++) {
        const int col = n0 + wn * 64 + nt * 8 + cq;
        float2 bsum;
        bsum.x = bih[col]     + bhh[col];
        bsum.y = bih[col + 1] + bhh[col + 1];
#pragma unroll
        for (int mt = 0; mt < 2; mt++) {
            const size_t r0 = m0 + wm * 32 + mt * 16 + rq;
            float2 v0 = make_float2(acc[mt][nt][0] + bsum.x, acc[mt][nt][1] + bsum.y);
            float2 v1 = make_float2(acc[mt][nt][2] + bsum.x, acc[mt][nt][3] + bsum.y);
            *(float2*)&g_gates[r0 * NGATE + col]       = v0;
            *(float2*)&g_gates[(r0 + 8) * NGATE + col] = v1;
        }
    }
}

// ---------------------------------------------------------------------------
// Kernel B: persistent recurrence, CTA tile M16 x N64, shfl epilogue.
// 128 CTAs = 4 batch groups x 32 j-tiles. 128 thr, 4 warps (N16 each).
// N-col c (CTA-local, 0..63): gate = c&3, jj = c>>2 (from W staging layout).
// ---------------------------------------------------------------------------
__device__ __forceinline__ float fsig(float x) {
    return __fdividef(1.0f, 1.0f + __expf(-x));
}
__device__ __forceinline__ float ftanh(float x) {
    x = fminf(fmaxf(x, -15.0f), 15.0f);
    float e = __expf(-2.0f * x);
    return __fdividef(1.0f - e, 1.0f + e);
}

#define RSTR    1040
#define OFF_WHI 0
#define OFF_WLO (64 * RSTR)              // 66560
#define OFF_HHI (2 * 64 * RSTR)          // 133120
#define OFF_HLO (OFF_HHI + 16 * RSTR)    // 149760
#define REC_SMEM (OFF_HLO + 16 * RSTR)   // 166400 -> 1 CTA/SM

__global__ __launch_bounds__(128, 1)
void lstm_rec(const float* __restrict__ c0,
              const float* __restrict__ Whh,
              float* __restrict__ out)
{
    extern __shared__ char smem[];
    const uint32_t sbase = smem_u32(smem);

    const int tid  = threadIdx.x;
    const int cb   = blockIdx.x;
    const int grp  = cb >> 5;            // batch group 0..3
    const int b0   = grp * 16;
    const int j0   = (cb & 31) * 16;     // 16 j's per CTA
    const int wid  = tid >> 5, lane = tid & 31;

    // --- stage W_hh (split bf16 hi/lo) once: 64 rows (n = jj*4+gate) x 512 ---
#pragma unroll 8
    for (int i = 0; i < 64; i++) {
        int idx = tid + i * 128;
        int row = idx >> 7, c4 = idx & 127;
        int R = (row & 3) * HDIM + j0 + (row >> 2);   // gate*512 + j0 + jj
        float4 v = *(const float4*)&Whh[(size_t)R * HDIM + c4 * 4];
        float f[4] = {v.x, v.y, v.z, v.w};
        __nv_bfloat16 h[4], l[4];
#pragma unroll
        for (int q = 0; q < 4; q++) {
            h[q] = __float2bfloat16_rn(f[q]);
            l[q] = __float2bfloat16_rn(f[q] - __bfloat162float(h[q]));
        }
        *(uint2*)(smem + OFF_WHI + row * RSTR + c4 * 8) = *(uint2*)h;
        *(uint2*)(smem + OFF_WLO + row * RSTR + c4 * 8) = *(uint2*)l;
    }

    // --- per-thread cell mapping (post-shfl):
    //   r = lane>>2 -> batches bA=b0+r, bB=b0+r+8
    //   quad q = lane&3: nt = q&1 (n-tile), jt = q>>1 (j within tile)
    //   jloc = wid*4 + nt*2 + jt  -> j = j0 + jloc
    const int r   = lane >> 2;
    const int up  = lane & 1;            // own gate pair: up? (g2,g3) : (g0,g1)
    const int jloc = wid * 4 + (lane & 1) * 2 + ((lane >> 1) & 1);
    const int j   = j0 + jloc;
    const int bA  = b0 + r;
    const int bB  = b0 + r + 8;

    float cA = c0[bA * HDIM + j];
    float cB = c0[bB * HDIM + j];
    float hA = 0.0f, hB = 0.0f;

    // --- ldmatrix addresses (proven lane mapping) ---
    const int lm = lane >> 3, lr = lane & 7;
    const uint32_t aAddr = sbase + OFF_HHI
        + (uint32_t)(((lm & 1) * 8 + lr) * RSTR + (lm >> 1) * 16);
    const uint32_t bAddr = sbase + OFF_WHI
        + (uint32_t)((wid * 16 + (lm >> 1) * 8 + lr) * RSTR + (lm & 1) * 16);
    const uint32_t LOH = OFF_HLO - OFF_HHI;
    const uint32_t LOW = OFF_WLO - OFF_WHI;

    unsigned long long barp =
        (unsigned long long)__cvta_generic_to_global(&g_bar4[grp * 32]);

    // gx double buffer
    float gxc[8], gxn[8];
    {
        const float* gA = g_gates + (size_t)(0 * BATCH + bA) * NGATE + j;
        const float* gB = g_gates + (size_t)(0 * BATCH + bB) * NGATE + j;
        gxc[0] = __ldcs(gA);        gxc[1] = __ldcs(gA + 512);
        gxc[2] = __ldcs(gA + 1024); gxc[3] = __ldcs(gA + 1536);
        gxc[4] = __ldcs(gB);        gxc[5] = __ldcs(gB + 512);
        gxc[6] = __ldcs(gB + 1024); gxc[7] = __ldcs(gB + 1536);
    }

    for (int t = 0; t < TSTEPS; t++) {
        // stage h hi (group 0) then lo (group 1) as separate cp.async groups
        const __nv_bfloat16* shi = g_hbuf_hi[t & 1] + (size_t)b0 * HDIM;
        const __nv_bfloat16* slo = g_hbuf_lo[t & 1] + (size_t)b0 * HDIM;
#pragma unroll
        for (int i = 0; i < 8; i++) {
            int idx = tid + i * 128;
            int row = idx >> 6, c = idx & 63;
            uint32_t doff = (uint32_t)(row * RSTR + c * 16);
            asm volatile("cp.async.cg.shared.global [%0],[%1],16;"
                         :: "r"(sbase + OFF_HHI + doff), "l"(shi + row * 512 + c * 8));
        }
        asm volatile("cp.async.commit_group;");
#pragma unroll
        for (int i = 0; i < 8; i++) {
            int idx = tid + i * 128;
            int row = idx >> 6, c = idx & 63;
            uint32_t doff = (uint32_t)(row * RSTR + c * 16);
            asm volatile("cp.async.cg.shared.global [%0],[%1],16;"
                         :: "r"(sbase + OFF_HLO + doff), "l"(slo + row * 512 + c * 8));
        }
        asm volatile("cp.async.commit_group;");

        asm volatile("cp.async.wait_group 1;");   // hi ready; lo in flight
        __syncthreads();

        float accP[8], accQ[8];
#pragma unroll
        for (int q = 0; q < 8; q++) { accP[q] = 0.0f; accQ[q] = 0.0f; }

        // loop1: terms needing only h-hi (lo copy overlaps this)
#pragma unroll 8
        for (int ks = 0; ks < 32; ks++) {
            const uint32_t ko = (uint32_t)(ks * 32);
            uint32_t ahi[4], bhi[4], blo[4];
            ldsm4(ahi, aAddr + ko);
            ldsm4(bhi, bAddr + ko);
            ldsm4(blo, bAddr + LOW + ko);
            hmma(accP + 0, ahi, bhi + 0);
            hmma(accP + 4, ahi, bhi + 2);
            hmma(accQ + 0, ahi, blo + 0);
            hmma(accQ + 4, ahi, blo + 2);
        }

        asm volatile("cp.async.wait_group 0;");   // lo ready (likely already)
        __syncthreads();

        // loop2: alo x Whi term
#pragma unroll 8
        for (int ks = 0; ks < 32; ks++) {
            const uint32_t ko = (uint32_t)(ks * 32);
            uint32_t alo[4], bhi[4];
            ldsm4(alo, aAddr + LOH + ko);
            ldsm4(bhi, bAddr + ko);
            hmma(accQ + 0, alo, bhi + 0);
            hmma(accQ + 4, alo, bhi + 2);
        }

        // --- shfl gate exchange (replaces accbuf STS/LDS + 2 syncthreads) ---
        float s[8];
#pragma unroll
        for (int q = 0; q < 8; q++) s[q] = accP[q] + accQ[q];
        // send my values of the PARTNER's tile; keep my own tile's
        float v0 = up ? s[0] : s[4];
        float v1 = up ? s[1] : s[5];
        float v2 = up ? s[2] : s[6];
        float v3 = up ? s[3] : s[7];
        float rc0 = __shfl_xor_sync(0xffffffffu, v0, 1);
        float rc1 = __shfl_xor_sync(0xffffffffu, v1, 1);
        float rc2 = __shfl_xor_sync(0xffffffffu, v2, 1);
        float rc3 = __shfl_xor_sync(0xffffffffu, v3, 1);
        float o0 = up ? s[4] : s[0];
        float o1 = up ? s[5] : s[1];
        float o2 = up ? s[6] : s[2];
        float o3 = up ? s[7] : s[3];
        // row r (cell A) gates g0..g3 ; row r+8 (cell B)
        float gA0 = up ? rc0 : o0;
        float gA1 = up ? rc1 : o1;
        float gA2 = up ? o0  : rc0;
        float gA3 = up ? o1  : rc1;
        float gB0 = up ? rc2 : o2;
        float gB1 = up ? rc3 : o3;
        float gB2 = up ? o2  : rc2;
        float gB3 = up ? o3  : rc3;

        // --- pointwise ---
        {
            float gi = fsig (gxc[0] + gA0);
            float gf = fsig (gxc[1] + gA1);
            float gg = ftanh(gxc[2] + gA2);
            float go = fsig (gxc[3] + gA3);
            cA = gf * cA + gi * gg;
            hA = go * ftanh(cA);

            gi = fsig (gxc[4] + gB0);
            gf = fsig (gxc[5] + gB1);
            gg = ftanh(gxc[6] + gB2);
            go = fsig (gxc[7] + gB3);
            cB = gf * cB + gi * gg;
            hB = go * ftanh(cB);
        }

        // publish h (hi/lo bf16) -- critical path
        {
            const int nb = (t + 1) & 1;
            __nv_bfloat16 pA = __float2bfloat16_rn(hA);
            __nv_bfloat16 pB = __float2bfloat16_rn(hB);
            g_hbuf_hi[nb][bA * HDIM + j] = pA;
            g_hbuf_hi[nb][bB * HDIM + j] = pB;
            g_hbuf_lo[nb][bA * HDIM + j] =
                __float2bfloat16_rn(hA - __bfloat162float(pA));
            g_hbuf_lo[nb][bB * HDIM + j] =
                __float2bfloat16_rn(hB - __bfloat162float(pB));
        }
        __syncthreads();                 // all publishes issued
        if (tid == 0) {
            // release-RED orders all CTA threads' prior stores (after bar.sync)
            asm volatile("red.release.gpu.global.add.u32 [%0], %1;"
                         :: "l"(barp), "r"(1u) : "memory");
        }

        // off-critical-path: outputs + gx prefetch for t+1
        out[(size_t)t * (BATCH * HDIM) + bA * HDIM + j] = hA;
        out[(size_t)t * (BATCH * HDIM) + bB * HDIM + j] = hB;
        {
            int tn = (t + 1 < TSTEPS) ? (t + 1) : t;
            const float* gA = g_gates + (size_t)(tn * BATCH + bA) * NGATE + j;
            const float* gB = g_gates + (size_t)(tn * BATCH + bB) * NGATE + j;
            gxn[0] = __ldcs(gA);        gxn[1] = __ldcs(gA + 512);
            gxn[2] = __ldcs(gA + 1024); gxn[3] = __ldcs(gA + 1536);
            gxn[4] = __ldcs(gB);        gxn[5] = __ldcs(gB + 512);
            gxn[6] = __ldcs(gB + 1024); gxn[7] = __ldcs(gB + 1536);
        }

        if (tid == 0) {
            const unsigned target = (unsigned)(t + 1) * 32;
            unsigned v;
            do {
                asm volatile("ld.acquire.gpu.global.u32 %0, [%1];"
                             : "=r"(v) : "l"(barp) : "memory");
            } while (v < target);
        }
        __syncthreads();

#pragma unroll
        for (int q = 0; q < 8; q++) gxc[q] = gxn[q];
    }

    const size_t obase = (size_t)TSTEPS * (BATCH * HDIM);
    out[obase + bA * HDIM + j] = hA;
    out[obase + bB * HDIM + j] = hB;
    out[obase + BATCH * HDIM + bA * HDIM + j] = cA;
    out[obase + BATCH * HDIM + bB * HDIM + j] = cB;
}

// ---------------------------------------------------------------------------
extern "C" void kernel_launch(void* const* d_in, const int* in_sizes, int n_in,
                              void* d_out, int out_size) {
    const float* inp = (const float*)d_in[0];
    const float* h0  = (const float*)d_in[1];
    const float* c0  = (const float*)d_in[2];
    const float* Wih = (const float*)d_in[3];
    const float* Whh = (const float*)d_in[4];
    const float* bih = (const float*)d_in[5];
    const float* bhh = (const float*)d_in[6];
    float* out = (float*)d_out;

    cudaFuncSetAttribute(gemm_mma, cudaFuncAttributeMaxDynamicSharedMemorySize,
                         GEMM_SMEM);
    cudaFuncSetAttribute(lstm_rec, cudaFuncAttributeMaxDynamicSharedMemorySize,
                         REC_SMEM);

    __nv_bfloat16 *ahi, *alo, *bhi, *blo;
    cudaGetSymbolAddress((void**)&ahi, g_Ahi);
    cudaGetSymbolAddress((void**)&alo, g_Alo);
    cudaGetSymbolAddress((void**)&bhi, g_Bhi);
    cudaGetSymbolAddress((void**)&blo, g_Blo);

    split_kernel<<<(MROWS * IDIM / 4 + 255) / 256, 256>>>(inp, ahi, alo,
                                                          MROWS * IDIM / 4);
    split_kernel<<<(NGATE * IDIM / 4 + 255) / 256, 256>>>(Wih, bhi, blo,
                                                          NGATE * IDIM / 4);

    dim3 gridA(NGATE / 128, MROWS / 128);
    gemm_mma<<<gridA, 256, GEMM_SMEM>>>(bih, bhh);

    init_kernel<<<(BATCH * HDIM + 255) / 256, 256>>>(h0);
    lstm_rec<<<NBLK, 128, REC_SMEM>>>(c0, Whh, out);
}